// round 1
// baseline (speedup 1.0000x reference)
#include <cuda_runtime.h>
#include <cstdint>

// Problem constants
#define B_  2
#define L_  2048
#define DM_ 1024
#define E_  2048
#define N_  16
#define KC_ 4
#define R_  64
#define BL_ (B_ * L_)   // 4096
#define E2_ (2 * E_)    // 4096

// ---------------- scratch (static device memory; no allocs allowed) --------
__device__ float g_xn  [BL_ * DM_];     // 16 MB  rmsnorm output
__device__ float g_xz  [BL_ * E2_];     // 64 MB  in_proj output (u_pre | z)
__device__ float g_u   [BL_ * E_];      // 32 MB  post conv+silu
__device__ float g_xdbl[BL_ * 96];      // 1.5 MB x_proj output (dt_low|B|C)
__device__ float g_dt  [BL_ * E_];      // 32 MB  softplus(dt)
__device__ float g_y   [BL_ * E_];      // 32 MB  gated scan output

// ---------------- RMSNorm ---------------------------------------------------
__global__ void rmsnorm_kernel(const float* __restrict__ x,
                               const float* __restrict__ w) {
    int row = blockIdx.x;
    const float* xr = x + (size_t)row * DM_;
    float s = 0.f;
    for (int i = threadIdx.x; i < DM_; i += 256) { float v = xr[i]; s += v * v; }
    __shared__ float red[8];
    for (int o = 16; o; o >>= 1) s += __shfl_xor_sync(0xffffffffu, s, o);
    if ((threadIdx.x & 31) == 0) red[threadIdx.x >> 5] = s;
    __syncthreads();
    if (threadIdx.x < 8) {
        float v = red[threadIdx.x];
        for (int o = 4; o; o >>= 1) v += __shfl_xor_sync(0xffu, v, o);
        if (threadIdx.x == 0) red[0] = v;
    }
    __syncthreads();
    float inv = rsqrtf(red[0] * (1.f / DM_) + 1e-5f);
    float* outr = g_xn + (size_t)row * DM_;
    for (int i = threadIdx.x; i < DM_; i += 256) outr[i] = xr[i] * inv * w[i];
}

// ---------------- generic GEMM: C[m,n] = sum_k A[m,k]*B[n,k] (+epilogue) ----
// A: M x K (row stride lda), B: N x K (row stride ldb), C: M x N (row stride ldc)
// MODE 0: plain   MODE 1: softplus(v + bias[n])   MODE 2: v + resid[m*ldc+n]
template <int MODE>
__global__ __launch_bounds__(256) void gemm_tn(
    const float* __restrict__ A, int lda,
    const float* __restrict__ B, int ldb,
    const float* __restrict__ bias,
    const float* __restrict__ resid,
    float* __restrict__ C, int ldc, int Kd) {
    const int BK = 16;
    __shared__ float As[BK][128];
    __shared__ float Bs[BK][128];
    int bm = blockIdx.y * 128, bn = blockIdx.x * 128;
    int tid = threadIdx.x;
    int tx = tid & 15, ty = tid >> 4;
    int lr = tid >> 2;            // 0..63
    int lc = (tid & 3) * 4;       // 0,4,8,12
    const float* Ap = A + (size_t)bm * lda;
    const float* Bp = B + (size_t)bn * ldb;
    float acc[8][8];
#pragma unroll
    for (int i = 0; i < 8; i++)
#pragma unroll
        for (int j = 0; j < 8; j++) acc[i][j] = 0.f;

    for (int k0 = 0; k0 < Kd; k0 += BK) {
        float4 a0 = *(const float4*)(Ap + (size_t)lr * lda + k0 + lc);
        float4 a1 = *(const float4*)(Ap + (size_t)(lr + 64) * lda + k0 + lc);
        float4 b0 = *(const float4*)(Bp + (size_t)lr * ldb + k0 + lc);
        float4 b1 = *(const float4*)(Bp + (size_t)(lr + 64) * ldb + k0 + lc);
        As[lc + 0][lr] = a0.x; As[lc + 1][lr] = a0.y;
        As[lc + 2][lr] = a0.z; As[lc + 3][lr] = a0.w;
        As[lc + 0][lr + 64] = a1.x; As[lc + 1][lr + 64] = a1.y;
        As[lc + 2][lr + 64] = a1.z; As[lc + 3][lr + 64] = a1.w;
        Bs[lc + 0][lr] = b0.x; Bs[lc + 1][lr] = b0.y;
        Bs[lc + 2][lr] = b0.z; Bs[lc + 3][lr] = b0.w;
        Bs[lc + 0][lr + 64] = b1.x; Bs[lc + 1][lr + 64] = b1.y;
        Bs[lc + 2][lr + 64] = b1.z; Bs[lc + 3][lr + 64] = b1.w;
        __syncthreads();
#pragma unroll
        for (int k = 0; k < BK; k++) {
            float ar[8], br[8];
#pragma unroll
            for (int i = 0; i < 8; i++) ar[i] = As[k][ty * 8 + i];
#pragma unroll
            for (int j = 0; j < 8; j++) br[j] = Bs[k][tx * 8 + j];
#pragma unroll
            for (int i = 0; i < 8; i++)
#pragma unroll
                for (int j = 0; j < 8; j++) acc[i][j] = fmaf(ar[i], br[j], acc[i][j]);
        }
        __syncthreads();
    }
#pragma unroll
    for (int i = 0; i < 8; i++) {
        int m = bm + ty * 8 + i;
#pragma unroll
        for (int j = 0; j < 8; j++) {
            int n = bn + tx * 8 + j;
            float v = acc[i][j];
            if (MODE == 1) {
                v += bias[n];
                v = (v > 20.f) ? v : log1pf(__expf(v));   // softplus
            }
            if (MODE == 2) v += resid[(size_t)m * ldc + n];
            C[(size_t)m * ldc + n] = v;
        }
    }
}

// ---------------- causal depthwise conv (K=4) + SiLU ------------------------
__global__ void conv_silu_kernel(const float* __restrict__ conv_w,
                                 const float* __restrict__ conv_b) {
    int idx = blockIdx.x * 256 + threadIdx.x;   // over BL_*E_
    int e = idx & (E_ - 1);
    int m = idx >> 11;            // b*L + t
    int t = m & (L_ - 1);
    float acc = conv_b[e];
    const float* base = g_xz + (size_t)m * E2_ + e;   // u_pre lives in cols [0,E)
#pragma unroll
    for (int j = 0; j < KC_; j++) {
        int ts = t - (KC_ - 1) + j;
        if (ts >= 0) acc = fmaf(conv_w[e * KC_ + j], base[(j - (KC_ - 1)) * E2_], acc);
    }
    g_u[(size_t)m * E_ + e] = acc / (1.f + __expf(-acc));   // silu
}

// ---------------- x_proj: x_dbl[m,f] = sum_e u[m,e]*W[f,e], f<96 -----------
__global__ __launch_bounds__(256) void xproj_kernel(const float* __restrict__ W) {
    const int BK = 32;
    __shared__ float As[BK][32];
    __shared__ float Bs[BK][96];
    int bm = blockIdx.x * 32;
    int tid = threadIdx.x;
    int tx = tid & 31;       // n-tile (3 cols each)
    int ty = tid >> 5;       // m-tile (4 rows each)
    float acc[4][3];
#pragma unroll
    for (int i = 0; i < 4; i++)
#pragma unroll
        for (int j = 0; j < 3; j++) acc[i][j] = 0.f;

    int alr = tid >> 3, alc = (tid & 7) * 4;   // A: 32 rows x 8 float4
    for (int k0 = 0; k0 < E_; k0 += BK) {
        float4 a = *(const float4*)(g_u + (size_t)(bm + alr) * E_ + k0 + alc);
        As[alc + 0][alr] = a.x; As[alc + 1][alr] = a.y;
        As[alc + 2][alr] = a.z; As[alc + 3][alr] = a.w;
#pragma unroll
        for (int r = 0; r < 3; r++) {
            int s = tid + r * 256;          // 768 float4 slots
            int fr = s >> 3, fc = (s & 7) * 4;
            float4 b = *(const float4*)(W + (size_t)fr * E_ + k0 + fc);
            Bs[fc + 0][fr] = b.x; Bs[fc + 1][fr] = b.y;
            Bs[fc + 2][fr] = b.z; Bs[fc + 3][fr] = b.w;
        }
        __syncthreads();
#pragma unroll
        for (int k = 0; k < BK; k++) {
            float ar[4], br[3];
#pragma unroll
            for (int i = 0; i < 4; i++) ar[i] = As[k][ty * 4 + i];
#pragma unroll
            for (int j = 0; j < 3; j++) br[j] = Bs[k][tx * 3 + j];
#pragma unroll
            for (int i = 0; i < 4; i++)
#pragma unroll
                for (int j = 0; j < 3; j++) acc[i][j] = fmaf(ar[i], br[j], acc[i][j]);
        }
        __syncthreads();
    }
#pragma unroll
    for (int i = 0; i < 4; i++)
#pragma unroll
        for (int j = 0; j < 3; j++)
            g_xdbl[(size_t)(bm + ty * 4 + i) * 96 + tx * 3 + j] = acc[i][j];
}

// ---------------- selective scan + D skip + silu(z) gate --------------------
// thread layout: lane n = tid&15 (state dim), c = tid>>4 (channel within block of 8)
__global__ __launch_bounds__(128) void scan_kernel(const float* __restrict__ A_log,
                                                   const float* __restrict__ Dp) {
    const int CH = 8;                // channels per block
    int b  = blockIdx.x / (E_ / CH);
    int e0 = (blockIdx.x % (E_ / CH)) * CH;
    int tid = threadIdx.x;
    int n = tid & 15, c = tid >> 4;
    int e = e0 + c;
    float a   = -__expf(A_log[e * N_ + n]);
    float d_e = Dp[e];
    float h = 0.f;
    __shared__ float s_dt[32][CH], s_u[32][CH], s_z[32][CH], s_bc[32][32];

    for (int t0 = 0; t0 < L_; t0 += 32) {
#pragma unroll
        for (int r = 0; r < 2; r++) {              // 256 elems / 128 threads
            int idx = tid + r * 128;
            int tt = idx >> 3, cc = idx & 7;
            int m = b * L_ + t0 + tt;
            size_t g = (size_t)m * E_ + e0 + cc;
            s_dt[tt][cc] = g_dt[g];
            s_u[tt][cc]  = g_u[g];
            s_z[tt][cc]  = g_xz[(size_t)m * E2_ + E_ + e0 + cc];
        }
#pragma unroll
        for (int r = 0; r < 8; r++) {              // 1024 elems
            int idx = tid + r * 128;
            int tt = idx >> 5, cc = idx & 31;
            s_bc[tt][cc] = g_xdbl[(size_t)(b * L_ + t0 + tt) * 96 + 64 + cc];
        }
        __syncthreads();
#pragma unroll 4
        for (int tt = 0; tt < 32; tt++) {
            float dtv = s_dt[tt][c];
            float uv  = s_u[tt][c];
            float Bv  = s_bc[tt][n];
            float Cv  = s_bc[tt][16 + n];
            float dA  = __expf(dtv * a);
            h = fmaf(h, dA, dtv * uv * Bv);
            float yp = h * Cv;
            yp += __shfl_xor_sync(0xffffffffu, yp, 8);
            yp += __shfl_xor_sync(0xffffffffu, yp, 4);
            yp += __shfl_xor_sync(0xffffffffu, yp, 2);
            yp += __shfl_xor_sync(0xffffffffu, yp, 1);
            if (n == 0) {
                float zv = s_z[tt][c];
                float yv = fmaf(uv, d_e, yp);
                yv = yv * (zv / (1.f + __expf(-zv)));
                g_y[(size_t)(b * L_ + t0 + tt) * E_ + e] = yv;
            }
        }
        __syncthreads();
    }
}

// ---------------- launch ----------------------------------------------------
extern "C" void kernel_launch(void* const* d_in, const int* in_sizes, int n_in,
                              void* d_out, int out_size) {
    const float* x         = (const float*)d_in[0];
    const float* norm_w    = (const float*)d_in[1];
    const float* in_proj_w = (const float*)d_in[2];
    const float* conv_w    = (const float*)d_in[3];
    const float* conv_b    = (const float*)d_in[4];
    const float* x_proj_w  = (const float*)d_in[5];
    const float* dt_proj_w = (const float*)d_in[6];
    const float* dt_proj_b = (const float*)d_in[7];
    const float* A_log     = (const float*)d_in[8];
    const float* Dp        = (const float*)d_in[9];
    const float* out_proj_w= (const float*)d_in[10];
    float* out = (float*)d_out;

    float *p_xn, *p_xz, *p_y;
    cudaGetSymbolAddress((void**)&p_xn, g_xn);
    cudaGetSymbolAddress((void**)&p_xz, g_xz);
    cudaGetSymbolAddress((void**)&p_y,  g_y);
    float* p_dt; cudaGetSymbolAddress((void**)&p_dt, g_dt);
    float* p_xdbl; cudaGetSymbolAddress((void**)&p_xdbl, g_xdbl);

    // 1) RMSNorm
    rmsnorm_kernel<<<BL_, 256>>>(x, norm_w);
    // 2) in_proj: xz[4096,4096] = xn @ in_proj_w^T
    gemm_tn<0><<<dim3(E2_ / 128, BL_ / 128), 256>>>(
        p_xn, DM_, in_proj_w, DM_, nullptr, nullptr, p_xz, E2_, DM_);
    // 3) depthwise causal conv + SiLU -> u
    conv_silu_kernel<<<(BL_ * E_) / 256, 256>>>(conv_w, conv_b);
    // 4) x_proj -> x_dbl [4096,96]
    xproj_kernel<<<BL_ / 32, 256>>>(x_proj_w);
    // 5) dt = softplus(dt_low @ dt_proj_w^T + b) [4096,2048]
    gemm_tn<1><<<dim3(E_ / 128, BL_ / 128), 256>>>(
        p_xdbl, 96, dt_proj_w, R_, dt_proj_b, nullptr, p_dt, E_, R_);
    // 6) selective scan fused with D skip and silu(z) gating -> y
    scan_kernel<<<B_ * (E_ / 8), 128>>>(A_log, Dp);
    // 7) out_proj + residual
    gemm_tn<2><<<dim3(DM_ / 128, BL_ / 128), 256>>>(
        p_y, E_, out_proj_w, E_, nullptr, x, out, DM_, E_);
}

// round 3
// speedup vs baseline: 1.0852x; 1.0852x over previous
#include <cuda_runtime.h>
#include <cuda_bf16.h>
#include <cstdint>

// Problem constants
#define B_  2
#define L_  2048
#define DM_ 1024
#define E_  2048
#define N_  16
#define KC_ 4
#define R_  64
#define BL_ (B_ * L_)   // 4096
#define E2_ (2 * E_)    // 4096

// ---------------- scratch (static device memory) ----------------------------
__device__ float g_xz  [BL_ * E2_];          // in_proj output (u_pre | z)
__device__ float g_u   [BL_ * E_];           // post conv+silu
__device__ float g_xdbl[BL_ * 96];           // x_proj output (dt_low|B|C)
__device__ float g_xp  [4 * BL_ * 96];       // x_proj split-K partials
__device__ float g_dt  [BL_ * E_];           // softplus(dt)
__device__ __nv_bfloat16 g_xnh[BL_ * DM_], g_xnl[BL_ * DM_];   // rmsnorm hi/lo
__device__ __nv_bfloat16 g_wih[E2_ * DM_],  g_wil[E2_ * DM_];  // in_proj_w hi/lo
__device__ __nv_bfloat16 g_yh [BL_ * E_],   g_yl [BL_ * E_];   // scan out hi/lo
__device__ __nv_bfloat16 g_woh[DM_ * E_],   g_wol[DM_ * E_];   // out_proj_w hi/lo

// ---------------- PTX helpers -----------------------------------------------
__device__ __forceinline__ uint32_t smem_u32(const void* p) {
    return (uint32_t)__cvta_generic_to_shared(p);
}
__device__ __forceinline__ void cp_async16(uint32_t dst, const void* src) {
    asm volatile("cp.async.cg.shared.global [%0], [%1], 16;\n" :: "r"(dst), "l"(src));
}
#define CP_COMMIT() asm volatile("cp.async.commit_group;\n" ::: "memory")
#define CP_WAIT(n)  asm volatile("cp.async.wait_group %0;\n" :: "n"(n) : "memory")

#define LDSM4(r0, r1, r2, r3, addr) \
    asm volatile("ldmatrix.sync.aligned.m8n8.x4.shared.b16 {%0,%1,%2,%3}, [%4];" \
        : "=r"(r0), "=r"(r1), "=r"(r2), "=r"(r3) : "r"(addr))

#define MMA16816(c, a, b) \
    asm volatile("mma.sync.aligned.m16n8k16.row.col.f32.bf16.bf16.f32 " \
        "{%0,%1,%2,%3}, {%4,%5,%6,%7}, {%8,%9}, {%0,%1,%2,%3};" \
        : "+f"((c)[0]), "+f"((c)[1]), "+f"((c)[2]), "+f"((c)[3]) \
        : "r"((a)[0]), "r"((a)[1]), "r"((a)[2]), "r"((a)[3]), "r"((b)[0]), "r"((b)[1]))

// ---------------- fp32 -> bf16 hi/lo split ----------------------------------
__global__ void split_kernel(const float* __restrict__ src,
                             __nv_bfloat16* __restrict__ hi,
                             __nv_bfloat16* __restrict__ lo, int n4) {
    int i = blockIdx.x * 256 + threadIdx.x;
    if (i >= n4) return;
    float4 v = ((const float4*)src)[i];
    float vv[4] = {v.x, v.y, v.z, v.w};
#pragma unroll
    for (int j = 0; j < 4; j++) {
        __nv_bfloat16 h = __float2bfloat16(vv[j]);
        hi[i * 4 + j] = h;
        lo[i * 4 + j] = __float2bfloat16(vv[j] - __bfloat162float(h));
    }
}

// ---------------- RMSNorm -> bf16 hi/lo --------------------------------------
__global__ void rmsnorm_kernel(const float* __restrict__ x,
                               const float* __restrict__ w) {
    int row = blockIdx.x;
    const float* xr = x + (size_t)row * DM_;
    float s = 0.f;
    for (int i = threadIdx.x; i < DM_; i += 256) { float v = xr[i]; s += v * v; }
    __shared__ float red[8];
    for (int o = 16; o; o >>= 1) s += __shfl_xor_sync(0xffffffffu, s, o);
    if ((threadIdx.x & 31) == 0) red[threadIdx.x >> 5] = s;
    __syncthreads();
    if (threadIdx.x < 8) {
        float v = red[threadIdx.x];
        for (int o = 4; o; o >>= 1) v += __shfl_xor_sync(0xffu, v, o);
        if (threadIdx.x == 0) red[0] = v;
    }
    __syncthreads();
    float inv = rsqrtf(red[0] * (1.f / DM_) + 1e-5f);
    size_t base = (size_t)row * DM_;
    for (int i = threadIdx.x; i < DM_; i += 256) {
        float v = xr[i] * inv * w[i];
        __nv_bfloat16 h = __float2bfloat16(v);
        g_xnh[base + i] = h;
        g_xnl[base + i] = __float2bfloat16(v - __bfloat162float(h));
    }
}

// ---------------- HMMA bf16x3 GEMM: C[m,n] = sum_k A[m,k]*B[n,k] ------------
// MODE 0: plain   MODE 2: + resid
// CTA tile 128x128, 8 warps (warp tile 64x32), K-chunk 64, 2-stage cp.async.
#define TILE_BYTES 16384
#define GEMM_SMEM  (1024 + 8 * TILE_BYTES)

template <int MODE>
__global__ __launch_bounds__(256) void gemm_bf16x3(
    const __nv_bfloat16* __restrict__ Ahi, const __nv_bfloat16* __restrict__ Alo, int lda,
    const __nv_bfloat16* __restrict__ Bhi, const __nv_bfloat16* __restrict__ Blo, int ldb,
    const float* __restrict__ resid, float* __restrict__ C, int ldc, int Kd) {
    extern __shared__ char smem[];
    uint32_t sb = smem_u32(smem);
    uint32_t tb0 = (sb + 1023u) & ~1023u;   // 1KB-aligned tile base (SW128)
    int tid = threadIdx.x, wid = tid >> 5, lid = tid & 31;
    int wm = wid >> 2, wn = wid & 3;        // warp grid 2(M) x 4(N)

    int bm = blockIdx.y * 128, bn = blockIdx.x * 128;
    const int NC = Kd >> 6;

    // tile loader: 128 rows x 128 bytes, SW128-swizzled, cp.async 16B
    auto load_tile = [&](uint32_t dst, const __nv_bfloat16* g, int row0, int ld, int k0) {
        const char* gp = (const char*)(g + (size_t)row0 * ld + k0);
#pragma unroll
        for (int it = 0; it < 4; it++) {
            int idx = tid + it * 256;
            int r = idx >> 3, c = (idx & 7) * 16;
            uint32_t off = (uint32_t)(r * 128 + c);
            off ^= ((off >> 3) & 0x70);
            cp_async16(dst + off, gp + (size_t)r * ld * 2 + c);
        }
    };
    auto load_chunk = [&](int stage, int k0) {
        uint32_t tb = tb0 + stage * 4 * TILE_BYTES;
        load_tile(tb,                  Ahi, bm, lda, k0);
        load_tile(tb + TILE_BYTES,     Alo, bm, lda, k0);
        load_tile(tb + 2 * TILE_BYTES, Bhi, bn, ldb, k0);
        load_tile(tb + 3 * TILE_BYTES, Blo, bn, ldb, k0);
        CP_COMMIT();
    };

    float acc[4][4][4];
#pragma unroll
    for (int i = 0; i < 4; i++)
#pragma unroll
        for (int j = 0; j < 4; j++)
#pragma unroll
            for (int q = 0; q < 4; q++) acc[i][j][q] = 0.f;

    load_chunk(0, 0);
    for (int ci = 0; ci < NC; ci++) {
        int s = ci & 1;
        if (ci + 1 < NC) { load_chunk((ci + 1) & 1, (ci + 1) * 64); CP_WAIT(1); }
        else             { CP_WAIT(0); }
        __syncthreads();
        uint32_t tA  = tb0 + s * 4 * TILE_BYTES;
        uint32_t tAl = tA + TILE_BYTES;
        uint32_t tB  = tA + 2 * TILE_BYTES;
        uint32_t tBl = tA + 3 * TILE_BYTES;
#pragma unroll
        for (int kk = 0; kk < 4; kk++) {
            uint32_t cb = (uint32_t)(kk * 32 + ((lid >> 4) << 4));
            uint32_t ah[4][4], al[4][4], bh[4][2], bl[4][2];
#pragma unroll
            for (int i = 0; i < 4; i++) {
                uint32_t off = (uint32_t)((wm * 64 + i * 16 + (lid & 15)) * 128) + cb;
                off ^= ((off >> 3) & 0x70);
                LDSM4(ah[i][0], ah[i][1], ah[i][2], ah[i][3], tA + off);
                LDSM4(al[i][0], al[i][1], al[i][2], al[i][3], tAl + off);
            }
#pragma unroll
            for (int jp = 0; jp < 2; jp++) {
                uint32_t off = (uint32_t)((wn * 32 + jp * 16 + (lid & 15)) * 128) + cb;
                off ^= ((off >> 3) & 0x70);
                uint32_t q0, q1, q2, q3;
                LDSM4(q0, q1, q2, q3, tB + off);
                bh[jp * 2][0] = q0; bh[jp * 2][1] = q2;
                bh[jp * 2 + 1][0] = q1; bh[jp * 2 + 1][1] = q3;
                LDSM4(q0, q1, q2, q3, tBl + off);
                bl[jp * 2][0] = q0; bl[jp * 2][1] = q2;
                bl[jp * 2 + 1][0] = q1; bl[jp * 2 + 1][1] = q3;
            }
#pragma unroll
            for (int i = 0; i < 4; i++)
#pragma unroll
                for (int j = 0; j < 4; j++) {
                    MMA16816(acc[i][j], ah[i], bh[j]);
                    MMA16816(acc[i][j], ah[i], bl[j]);
                    MMA16816(acc[i][j], al[i], bh[j]);
                }
        }
        __syncthreads();
    }

    // epilogue: fragment (i,j): rows bm+wm*64+i*16+{lid/4, +8}, cols bn+wn*32+j*8+(lid%4)*2
    int r0 = bm + wm * 64 + (lid >> 2);
    int c0 = bn + wn * 32 + (lid & 3) * 2;
#pragma unroll
    for (int i = 0; i < 4; i++) {
#pragma unroll
        for (int j = 0; j < 4; j++) {
            int r = r0 + i * 16, c = c0 + j * 8;
            float2 v0 = {acc[i][j][0], acc[i][j][1]};
            float2 v1 = {acc[i][j][2], acc[i][j][3]};
            if (MODE == 2) {
                const float2 q0 = *(const float2*)(resid + (size_t)r * ldc + c);
                const float2 q1 = *(const float2*)(resid + (size_t)(r + 8) * ldc + c);
                v0.x += q0.x; v0.y += q0.y; v1.x += q1.x; v1.y += q1.y;
            }
            *(float2*)(C + (size_t)r * ldc + c) = v0;
            *(float2*)(C + (size_t)(r + 8) * ldc + c) = v1;
        }
    }
}

// ---------------- fp32 FFMA GEMM (dt projection, K=64) ----------------------
template <int MODE>
__global__ __launch_bounds__(256) void gemm_tn(
    const float* __restrict__ A, int lda,
    const float* __restrict__ B, int ldb,
    const float* __restrict__ bias,
    const float* __restrict__ resid,
    float* __restrict__ C, int ldc, int Kd) {
    const int BK = 16;
    __shared__ float As[BK][128];
    __shared__ float Bs[BK][128];
    int bm = blockIdx.y * 128, bn = blockIdx.x * 128;
    int tid = threadIdx.x;
    int tx = tid & 15, ty = tid >> 4;
    int lr = tid >> 2;
    int lc = (tid & 3) * 4;
    const float* Ap = A + (size_t)bm * lda;
    const float* Bp = B + (size_t)bn * ldb;
    float acc[8][8];
#pragma unroll
    for (int i = 0; i < 8; i++)
#pragma unroll
        for (int j = 0; j < 8; j++) acc[i][j] = 0.f;

    for (int k0 = 0; k0 < Kd; k0 += BK) {
        float4 a0 = *(const float4*)(Ap + (size_t)lr * lda + k0 + lc);
        float4 a1 = *(const float4*)(Ap + (size_t)(lr + 64) * lda + k0 + lc);
        float4 b0 = *(const float4*)(Bp + (size_t)lr * ldb + k0 + lc);
        float4 b1 = *(const float4*)(Bp + (size_t)(lr + 64) * ldb + k0 + lc);
        As[lc + 0][lr] = a0.x; As[lc + 1][lr] = a0.y;
        As[lc + 2][lr] = a0.z; As[lc + 3][lr] = a0.w;
        As[lc + 0][lr + 64] = a1.x; As[lc + 1][lr + 64] = a1.y;
        As[lc + 2][lr + 64] = a1.z; As[lc + 3][lr + 64] = a1.w;
        Bs[lc + 0][lr] = b0.x; Bs[lc + 1][lr] = b0.y;
        Bs[lc + 2][lr] = b0.z; Bs[lc + 3][lr] = b0.w;
        Bs[lc + 0][lr + 64] = b1.x; Bs[lc + 1][lr + 64] = b1.y;
        Bs[lc + 2][lr + 64] = b1.z; Bs[lc + 3][lr + 64] = b1.w;
        __syncthreads();
#pragma unroll
        for (int k = 0; k < BK; k++) {
            float ar[8], br[8];
#pragma unroll
            for (int i = 0; i < 8; i++) ar[i] = As[k][ty * 8 + i];
#pragma unroll
            for (int j = 0; j < 8; j++) br[j] = Bs[k][tx * 8 + j];
#pragma unroll
            for (int i = 0; i < 8; i++)
#pragma unroll
                for (int j = 0; j < 8; j++) acc[i][j] = fmaf(ar[i], br[j], acc[i][j]);
        }
        __syncthreads();
    }
#pragma unroll
    for (int i = 0; i < 8; i++) {
        int m = bm + ty * 8 + i;
#pragma unroll
        for (int j = 0; j < 8; j++) {
            int n = bn + tx * 8 + j;
            float v = acc[i][j];
            if (MODE == 1) {
                v += bias[n];
                v = (v > 20.f) ? v : log1pf(__expf(v));
            }
            if (MODE == 2) v += resid[(size_t)m * ldc + n];
            C[(size_t)m * ldc + n] = v;
        }
    }
}

// ---------------- causal depthwise conv (K=4) + SiLU ------------------------
__global__ void conv_silu_kernel(const float* __restrict__ conv_w,
                                 const float* __restrict__ conv_b) {
    int idx = blockIdx.x * 256 + threadIdx.x;
    int e = idx & (E_ - 1);
    int m = idx >> 11;
    int t = m & (L_ - 1);
    float acc = conv_b[e];
    const float* base = g_xz + (size_t)m * E2_ + e;
#pragma unroll
    for (int j = 0; j < KC_; j++) {
        int ts = t - (KC_ - 1) + j;
        if (ts >= 0) acc = fmaf(conv_w[e * KC_ + j], base[(j - (KC_ - 1)) * E2_], acc);
    }
    g_u[(size_t)m * E_ + e] = acc / (1.f + __expf(-acc));
}

// ---------------- x_proj split-K partials: 4 x [BL, 96] ---------------------
__global__ __launch_bounds__(256) void xproj_part_kernel(const float* __restrict__ W) {
    const int BK = 32;
    __shared__ float As[BK][32];
    __shared__ float Bs[BK][96];
    int bm = blockIdx.x * 32;
    int kz = blockIdx.y;
    int tid = threadIdx.x;
    int tx = tid & 31;
    int ty = tid >> 5;
    float acc[4][3];
#pragma unroll
    for (int i = 0; i < 4; i++)
#pragma unroll
        for (int j = 0; j < 3; j++) acc[i][j] = 0.f;

    int alr = tid >> 3, alc = (tid & 7) * 4;
    int kbeg = kz * (E_ / 4), kend = kbeg + (E_ / 4);
    for (int k0 = kbeg; k0 < kend; k0 += BK) {
        float4 a = *(const float4*)(g_u + (size_t)(bm + alr) * E_ + k0 + alc);
        As[alc + 0][alr] = a.x; As[alc + 1][alr] = a.y;
        As[alc + 2][alr] = a.z; As[alc + 3][alr] = a.w;
#pragma unroll
        for (int r = 0; r < 3; r++) {
            int s = tid + r * 256;
            int fr = s >> 3, fc = (s & 7) * 4;
            float4 b = *(const float4*)(W + (size_t)fr * E_ + k0 + fc);
            Bs[fc + 0][fr] = b.x; Bs[fc + 1][fr] = b.y;
            Bs[fc + 2][fr] = b.z; Bs[fc + 3][fr] = b.w;
        }
        __syncthreads();
#pragma unroll
        for (int k = 0; k < BK; k++) {
            float ar[4], br[3];
#pragma unroll
            for (int i = 0; i < 4; i++) ar[i] = As[k][ty * 4 + i];
#pragma unroll
            for (int j = 0; j < 3; j++) br[j] = Bs[k][tx * 3 + j];
#pragma unroll
            for (int i = 0; i < 4; i++)
#pragma unroll
                for (int j = 0; j < 3; j++) acc[i][j] = fmaf(ar[i], br[j], acc[i][j]);
        }
        __syncthreads();
    }
    float* outp = g_xp + (size_t)kz * (BL_ * 96);
#pragma unroll
    for (int i = 0; i < 4; i++)
#pragma unroll
        for (int j = 0; j < 3; j++)
            outp[(size_t)(bm + ty * 4 + i) * 96 + tx * 3 + j] = acc[i][j];
}

__global__ void xproj_reduce_kernel() {
    int i = blockIdx.x * 256 + threadIdx.x;   // BL_*96 total
    const size_t S = (size_t)BL_ * 96;
    g_xdbl[i] = g_xp[i] + g_xp[i + S] + g_xp[i + 2 * S] + g_xp[i + 3 * S];
}

// ---------------- selective scan + D skip + silu(z) gate --------------------
__global__ __launch_bounds__(128) void scan_kernel(const float* __restrict__ A_log,
                                                   const float* __restrict__ Dp) {
    const int CH = 8;
    int b  = blockIdx.x / (E_ / CH);
    int e0 = (blockIdx.x % (E_ / CH)) * CH;
    int tid = threadIdx.x;
    int n = tid & 15, c = tid >> 4;
    int e = e0 + c;
    float a   = -__expf(A_log[e * N_ + n]);
    float d_e = Dp[e];
    float h = 0.f;
    __shared__ float s_dt[32][CH], s_u[32][CH], s_z[32][CH], s_bc[32][32];

    for (int t0 = 0; t0 < L_; t0 += 32) {
#pragma unroll
        for (int r = 0; r < 2; r++) {
            int idx = tid + r * 128;
            int tt = idx >> 3, cc = idx & 7;
            int m = b * L_ + t0 + tt;
            size_t g = (size_t)m * E_ + e0 + cc;
            s_dt[tt][cc] = g_dt[g];
            s_u[tt][cc]  = g_u[g];
            s_z[tt][cc]  = g_xz[(size_t)m * E2_ + E_ + e0 + cc];
        }
#pragma unroll
        for (int r = 0; r < 8; r++) {
            int idx = tid + r * 128;
            int tt = idx >> 5, cc = idx & 31;
            s_bc[tt][cc] = g_xdbl[(size_t)(b * L_ + t0 + tt) * 96 + 64 + cc];
        }
        __syncthreads();
#pragma unroll 4
        for (int tt = 0; tt < 32; tt++) {
            float dtv = s_dt[tt][c];
            float uv  = s_u[tt][c];
            float Bv  = s_bc[tt][n];
            float Cv  = s_bc[tt][16 + n];
            float dA  = __expf(dtv * a);
            h = fmaf(h, dA, dtv * uv * Bv);
            float yp = h * Cv;
            yp += __shfl_xor_sync(0xffffffffu, yp, 8);
            yp += __shfl_xor_sync(0xffffffffu, yp, 4);
            yp += __shfl_xor_sync(0xffffffffu, yp, 2);
            yp += __shfl_xor_sync(0xffffffffu, yp, 1);
            if (n == 0) {
                float zv = s_z[tt][c];
                float yv = fmaf(uv, d_e, yp);
                yv = yv * (zv / (1.f + __expf(-zv)));
                size_t off = (size_t)(b * L_ + t0 + tt) * E_ + e;
                __nv_bfloat16 hh = __float2bfloat16(yv);
                g_yh[off] = hh;
                g_yl[off] = __float2bfloat16(yv - __bfloat162float(hh));
            }
        }
        __syncthreads();
    }
}

// ---------------- launch ----------------------------------------------------
extern "C" void kernel_launch(void* const* d_in, const int* in_sizes, int n_in,
                              void* d_out, int out_size) {
    const float* x         = (const float*)d_in[0];
    const float* norm_w    = (const float*)d_in[1];
    const float* in_proj_w = (const float*)d_in[2];
    const float* conv_w    = (const float*)d_in[3];
    const float* conv_b    = (const float*)d_in[4];
    const float* x_proj_w  = (const float*)d_in[5];
    const float* dt_proj_w = (const float*)d_in[6];
    const float* dt_proj_b = (const float*)d_in[7];
    const float* A_log     = (const float*)d_in[8];
    const float* Dp        = (const float*)d_in[9];
    const float* out_proj_w= (const float*)d_in[10];
    float* out = (float*)d_out;

    float *p_xz, *p_dt, *p_xdbl;
    cudaGetSymbolAddress((void**)&p_xz,   g_xz);
    cudaGetSymbolAddress((void**)&p_dt,   g_dt);
    cudaGetSymbolAddress((void**)&p_xdbl, g_xdbl);
    __nv_bfloat16 *p_xnh, *p_xnl, *p_wih, *p_wil, *p_yh, *p_yl, *p_woh, *p_wol;
    cudaGetSymbolAddress((void**)&p_xnh, g_xnh);
    cudaGetSymbolAddress((void**)&p_xnl, g_xnl);
    cudaGetSymbolAddress((void**)&p_wih, g_wih);
    cudaGetSymbolAddress((void**)&p_wil, g_wil);
    cudaGetSymbolAddress((void**)&p_yh,  g_yh);
    cudaGetSymbolAddress((void**)&p_yl,  g_yl);
    cudaGetSymbolAddress((void**)&p_woh, g_woh);
    cudaGetSymbolAddress((void**)&p_wol, g_wol);

    cudaFuncSetAttribute(gemm_bf16x3<0>, cudaFuncAttributeMaxDynamicSharedMemorySize, GEMM_SMEM);
    cudaFuncSetAttribute(gemm_bf16x3<2>, cudaFuncAttributeMaxDynamicSharedMemorySize, GEMM_SMEM);

    // 0) weight splits (bf16 hi/lo)
    split_kernel<<<(E2_ * DM_ / 4 + 255) / 256, 256>>>(in_proj_w, p_wih, p_wil, E2_ * DM_ / 4);
    split_kernel<<<(DM_ * E_ / 4 + 255) / 256, 256>>>(out_proj_w, p_woh, p_wol, DM_ * E_ / 4);
    // 1) RMSNorm -> xn hi/lo
    rmsnorm_kernel<<<BL_, 256>>>(x, norm_w);
    // 2) in_proj (HMMA bf16x3): xz[4096,4096]
    gemm_bf16x3<0><<<dim3(E2_ / 128, BL_ / 128), 256, GEMM_SMEM>>>(
        p_xnh, p_xnl, DM_, p_wih, p_wil, DM_, nullptr, p_xz, E2_, DM_);
    // 3) depthwise causal conv + SiLU -> u
    conv_silu_kernel<<<(BL_ * E_) / 256, 256>>>(conv_w, conv_b);
    // 4) x_proj split-K x4 + reduce -> x_dbl [4096,96]
    xproj_part_kernel<<<dim3(BL_ / 32, 4), 256>>>(x_proj_w);
    xproj_reduce_kernel<<<(BL_ * 96) / 256, 256>>>();
    // 5) dt = softplus(dt_low @ dt_proj_w^T + b) [4096,2048]
    gemm_tn<1><<<dim3(E_ / 128, BL_ / 128), 256>>>(
        p_xdbl, 96, dt_proj_w, R_, dt_proj_b, nullptr, p_dt, E_, R_);
    // 6) selective scan -> y hi/lo
    scan_kernel<<<B_ * (E_ / 8), 128>>>(A_log, Dp);
    // 7) out_proj (HMMA bf16x3) + residual
    gemm_bf16x3<2><<<dim3(DM_ / 128, BL_ / 128), 256, GEMM_SMEM>>>(
        p_yh, p_yl, E_, p_woh, p_wol, E_, x, out, DM_, E_);
}

// round 4
// speedup vs baseline: 1.7405x; 1.6039x over previous
#include <cuda_runtime.h>
#include <cuda_bf16.h>
#include <cstdint>

// Problem constants
#define B_  2
#define L_  2048
#define DM_ 1024
#define E_  2048
#define N_  16
#define KC_ 4
#define R_  64
#define BL_ (B_ * L_)   // 4096
#define E2_ (2 * E_)    // 4096

// ---------------- scratch (static device memory) ----------------------------
__device__ float g_xz  [BL_ * E2_];          // in_proj output (u_pre | z)
__device__ float g_u   [BL_ * E_];           // post conv+silu
__device__ float g_xdbl[BL_ * 96];           // x_proj output (dt_low|B|C)
__device__ float g_xp  [4 * BL_ * 96];       // x_proj split-K partials
__device__ float g_dt  [BL_ * E_];           // softplus(dt)
__device__ float g_xn  [BL_ * DM_];          // rmsnorm out (tf32-rounded fp32)
__device__ float g_wi  [E2_ * DM_];          // in_proj_w  (tf32-rounded)
__device__ float g_wo  [DM_ * E_];           // out_proj_w (tf32-rounded)
__device__ float g_y   [BL_ * E_];           // scan out (tf32-rounded)

// ---------------- PTX helpers -----------------------------------------------
__device__ __forceinline__ uint32_t smem_u32(const void* p) {
    return (uint32_t)__cvta_generic_to_shared(p);
}
__device__ __forceinline__ void cp_async16(uint32_t dst, const void* src) {
    asm volatile("cp.async.cg.shared.global [%0], [%1], 16;\n" :: "r"(dst), "l"(src));
}
#define CP_COMMIT() asm volatile("cp.async.commit_group;\n" ::: "memory")
#define CP_WAIT(n)  asm volatile("cp.async.wait_group %0;\n" :: "n"(n) : "memory")

#define LDSM4(r0, r1, r2, r3, addr) \
    asm volatile("ldmatrix.sync.aligned.m8n8.x4.shared.b16 {%0,%1,%2,%3}, [%4];" \
        : "=r"(r0), "=r"(r1), "=r"(r2), "=r"(r3) : "r"(addr))
#define LDSM2(r0, r1, addr) \
    asm volatile("ldmatrix.sync.aligned.m8n8.x2.shared.b16 {%0,%1}, [%2];" \
        : "=r"(r0), "=r"(r1) : "r"(addr))

#define MMATF32(c, a, b) \
    asm volatile("mma.sync.aligned.m16n8k8.row.col.f32.tf32.tf32.f32 " \
        "{%0,%1,%2,%3}, {%4,%5,%6,%7}, {%8,%9}, {%0,%1,%2,%3};" \
        : "+f"((c)[0]), "+f"((c)[1]), "+f"((c)[2]), "+f"((c)[3]) \
        : "r"((a)[0]), "r"((a)[1]), "r"((a)[2]), "r"((a)[3]), "r"((b)[0]), "r"((b)[1]))

__device__ __forceinline__ float tf32_round(float v) {
    float o;
    asm("cvt.rna.tf32.f32 %0, %1;" : "=f"(o) : "f"(v));
    return o;
}

// ---------------- fp32 -> tf32-rounded fp32 copy ----------------------------
__global__ void cvt_tf32_kernel(const float* __restrict__ src,
                                float* __restrict__ dst, int n4) {
    int i = blockIdx.x * 256 + threadIdx.x;
    if (i >= n4) return;
    float4 v = ((const float4*)src)[i];
    v.x = tf32_round(v.x); v.y = tf32_round(v.y);
    v.z = tf32_round(v.z); v.w = tf32_round(v.w);
    ((float4*)dst)[i] = v;
}

// ---------------- RMSNorm -> tf32-rounded fp32 -------------------------------
__global__ void rmsnorm_kernel(const float* __restrict__ x,
                               const float* __restrict__ w) {
    int row = blockIdx.x;
    const float* xr = x + (size_t)row * DM_;
    float s = 0.f;
    for (int i = threadIdx.x; i < DM_; i += 256) { float v = xr[i]; s += v * v; }
    __shared__ float red[8];
    for (int o = 16; o; o >>= 1) s += __shfl_xor_sync(0xffffffffu, s, o);
    if ((threadIdx.x & 31) == 0) red[threadIdx.x >> 5] = s;
    __syncthreads();
    if (threadIdx.x < 8) {
        float v = red[threadIdx.x];
        for (int o = 4; o; o >>= 1) v += __shfl_xor_sync(0xffu, v, o);
        if (threadIdx.x == 0) red[0] = v;
    }
    __syncthreads();
    float inv = rsqrtf(red[0] * (1.f / DM_) + 1e-5f);
    size_t base = (size_t)row * DM_;
    for (int i = threadIdx.x; i < DM_; i += 256)
        g_xn[base + i] = tf32_round(xr[i] * inv * w[i]);
}

// ---------------- tf32 HMMA GEMM: C[m,n] = sum_k A[m,k]*B[n,k] --------------
// MODE 0: plain   MODE 2: + resid
// CTA 128x128, 8 warps (2Mx4N grid, warp tile 64x32), K-chunk 32 (fp32, 128B rows)
// 2-stage cp.async, 64KB smem -> 2 CTAs/SM.
#define TTILE 16384                  // one 128x32 fp32 tile
#define GEMM_SMEM (1024 + 4 * TTILE) // 2 stages x (A + B)

template <int MODE>
__global__ __launch_bounds__(256, 2) void gemm_tf32(
    const float* __restrict__ A, int lda,
    const float* __restrict__ B, int ldb,
    const float* __restrict__ resid, float* __restrict__ C, int ldc, int Kd) {
    extern __shared__ char smem[];
    uint32_t sb = smem_u32(smem);
    uint32_t tb0 = (sb + 1023u) & ~1023u;
    int tid = threadIdx.x, wid = tid >> 5, lid = tid & 31;
    int wm = wid >> 2, wn = wid & 3;

    int bm = blockIdx.y * 128, bn = blockIdx.x * 128;
    const int NC = Kd >> 5;

    // tile: 128 rows x 32 fp32 (128B rows), SW128-swizzled
    auto load_tile = [&](uint32_t dst, const float* g, int row0, int ld, int k0) {
#pragma unroll
        for (int it = 0; it < 4; it++) {
            int idx = tid + it * 256;
            int r = idx >> 3, c16 = idx & 7;
            uint32_t off = (uint32_t)(r * 128 + ((c16 ^ (r & 7)) << 4));
            cp_async16(dst + off, g + (size_t)(row0 + r) * ld + k0 + c16 * 4);
        }
    };
    auto load_chunk = [&](int stage, int k0) {
        uint32_t tb = tb0 + stage * 2 * TTILE;
        load_tile(tb,         A, bm, lda, k0);
        load_tile(tb + TTILE, B, bn, ldb, k0);
        CP_COMMIT();
    };

    float acc[4][4][4];
#pragma unroll
    for (int i = 0; i < 4; i++)
#pragma unroll
        for (int j = 0; j < 4; j++)
#pragma unroll
            for (int q = 0; q < 4; q++) acc[i][j][q] = 0.f;

    load_chunk(0, 0);
    for (int ci = 0; ci < NC; ci++) {
        int s = ci & 1;
        if (ci + 1 < NC) { load_chunk((ci + 1) & 1, (ci + 1) * 32); CP_WAIT(1); }
        else             { CP_WAIT(0); }
        __syncthreads();
        uint32_t tA = tb0 + s * 2 * TTILE;
        uint32_t tB = tA + TTILE;
#pragma unroll
        for (int kk = 0; kk < 4; kk++) {
            uint32_t a[4][4];
#pragma unroll
            for (int i = 0; i < 4; i++) {
                int row = wm * 64 + i * 16 + (lid & 15);
                uint32_t chunk = (uint32_t)((kk * 2 + (lid >> 4)) ^ (row & 7));
                LDSM4(a[i][0], a[i][1], a[i][2], a[i][3],
                      tA + (uint32_t)(row * 128) + (chunk << 4));
            }
#pragma unroll
            for (int j = 0; j < 4; j++) {
                int row = wn * 32 + j * 8 + (lid & 7);
                uint32_t chunk = (uint32_t)((kk * 2 + ((lid >> 3) & 1)) ^ (row & 7));
                uint32_t b[2];
                LDSM2(b[0], b[1], tB + (uint32_t)(row * 128) + (chunk << 4));
#pragma unroll
                for (int i = 0; i < 4; i++) MMATF32(acc[i][j], a[i], b);
            }
        }
        __syncthreads();
    }

    // epilogue
    int r0 = bm + wm * 64 + (lid >> 2);
    int c0 = bn + wn * 32 + (lid & 3) * 2;
#pragma unroll
    for (int i = 0; i < 4; i++) {
#pragma unroll
        for (int j = 0; j < 4; j++) {
            int r = r0 + i * 16, c = c0 + j * 8;
            float2 v0 = {acc[i][j][0], acc[i][j][1]};
            float2 v1 = {acc[i][j][2], acc[i][j][3]};
            if (MODE == 2) {
                const float2 q0 = *(const float2*)(resid + (size_t)r * ldc + c);
                const float2 q1 = *(const float2*)(resid + (size_t)(r + 8) * ldc + c);
                v0.x += q0.x; v0.y += q0.y; v1.x += q1.x; v1.y += q1.y;
            }
            *(float2*)(C + (size_t)r * ldc + c) = v0;
            *(float2*)(C + (size_t)(r + 8) * ldc + c) = v1;
        }
    }
}

// ---------------- fp32 FFMA GEMM (dt projection, K=64) ----------------------
template <int MODE>
__global__ __launch_bounds__(256) void gemm_tn(
    const float* __restrict__ A, int lda,
    const float* __restrict__ B, int ldb,
    const float* __restrict__ bias,
    const float* __restrict__ resid,
    float* __restrict__ C, int ldc, int Kd) {
    const int BK = 16;
    __shared__ float As[BK][128];
    __shared__ float Bs[BK][128];
    int bm = blockIdx.y * 128, bn = blockIdx.x * 128;
    int tid = threadIdx.x;
    int tx = tid & 15, ty = tid >> 4;
    int lr = tid >> 2;
    int lc = (tid & 3) * 4;
    const float* Ap = A + (size_t)bm * lda;
    const float* Bp = B + (size_t)bn * ldb;
    float acc[8][8];
#pragma unroll
    for (int i = 0; i < 8; i++)
#pragma unroll
        for (int j = 0; j < 8; j++) acc[i][j] = 0.f;

    for (int k0 = 0; k0 < Kd; k0 += BK) {
        float4 a0 = *(const float4*)(Ap + (size_t)lr * lda + k0 + lc);
        float4 a1 = *(const float4*)(Ap + (size_t)(lr + 64) * lda + k0 + lc);
        float4 b0 = *(const float4*)(Bp + (size_t)lr * ldb + k0 + lc);
        float4 b1 = *(const float4*)(Bp + (size_t)(lr + 64) * ldb + k0 + lc);
        As[lc + 0][lr] = a0.x; As[lc + 1][lr] = a0.y;
        As[lc + 2][lr] = a0.z; As[lc + 3][lr] = a0.w;
        As[lc + 0][lr + 64] = a1.x; As[lc + 1][lr + 64] = a1.y;
        As[lc + 2][lr + 64] = a1.z; As[lc + 3][lr + 64] = a1.w;
        Bs[lc + 0][lr] = b0.x; Bs[lc + 1][lr] = b0.y;
        Bs[lc + 2][lr] = b0.z; Bs[lc + 3][lr] = b0.w;
        Bs[lc + 0][lr + 64] = b1.x; Bs[lc + 1][lr + 64] = b1.y;
        Bs[lc + 2][lr + 64] = b1.z; Bs[lc + 3][lr + 64] = b1.w;
        __syncthreads();
#pragma unroll
        for (int k = 0; k < BK; k++) {
            float ar[8], br[8];
#pragma unroll
            for (int i = 0; i < 8; i++) ar[i] = As[k][ty * 8 + i];
#pragma unroll
            for (int j = 0; j < 8; j++) br[j] = Bs[k][tx * 8 + j];
#pragma unroll
            for (int i = 0; i < 8; i++)
#pragma unroll
                for (int j = 0; j < 8; j++) acc[i][j] = fmaf(ar[i], br[j], acc[i][j]);
        }
        __syncthreads();
    }
#pragma unroll
    for (int i = 0; i < 8; i++) {
        int m = bm + ty * 8 + i;
#pragma unroll
        for (int j = 0; j < 8; j++) {
            int n = bn + tx * 8 + j;
            float v = acc[i][j];
            if (MODE == 1) {
                v += bias[n];
                v = (v > 20.f) ? v : log1pf(__expf(v));
            }
            if (MODE == 2) v += resid[(size_t)m * ldc + n];
            C[(size_t)m * ldc + n] = v;
        }
    }
}

// ---------------- causal depthwise conv (K=4) + SiLU ------------------------
__global__ void conv_silu_kernel(const float* __restrict__ conv_w,
                                 const float* __restrict__ conv_b) {
    int idx = blockIdx.x * 256 + threadIdx.x;
    int e = idx & (E_ - 1);
    int m = idx >> 11;
    int t = m & (L_ - 1);
    float acc = conv_b[e];
    const float* base = g_xz + (size_t)m * E2_ + e;
#pragma unroll
    for (int j = 0; j < KC_; j++) {
        int ts = t - (KC_ - 1) + j;
        if (ts >= 0) acc = fmaf(conv_w[e * KC_ + j], base[(j - (KC_ - 1)) * E2_], acc);
    }
    g_u[(size_t)m * E_ + e] = acc / (1.f + __expf(-acc));
}

// ---------------- x_proj split-K partials: 4 x [BL, 96] ---------------------
__global__ __launch_bounds__(256) void xproj_part_kernel(const float* __restrict__ W) {
    const int BK = 32;
    __shared__ float As[BK][32];
    __shared__ float Bs[BK][96];
    int bm = blockIdx.x * 32;
    int kz = blockIdx.y;
    int tid = threadIdx.x;
    int tx = tid & 31;
    int ty = tid >> 5;
    float acc[4][3];
#pragma unroll
    for (int i = 0; i < 4; i++)
#pragma unroll
        for (int j = 0; j < 3; j++) acc[i][j] = 0.f;

    int alr = tid >> 3, alc = (tid & 7) * 4;
    int kbeg = kz * (E_ / 4), kend = kbeg + (E_ / 4);
    for (int k0 = kbeg; k0 < kend; k0 += BK) {
        float4 a = *(const float4*)(g_u + (size_t)(bm + alr) * E_ + k0 + alc);
        As[alc + 0][alr] = a.x; As[alc + 1][alr] = a.y;
        As[alc + 2][alr] = a.z; As[alc + 3][alr] = a.w;
#pragma unroll
        for (int r = 0; r < 3; r++) {
            int s = tid + r * 256;
            int fr = s >> 3, fc = (s & 7) * 4;
            float4 b = *(const float4*)(W + (size_t)fr * E_ + k0 + fc);
            Bs[fc + 0][fr] = b.x; Bs[fc + 1][fr] = b.y;
            Bs[fc + 2][fr] = b.z; Bs[fc + 3][fr] = b.w;
        }
        __syncthreads();
#pragma unroll
        for (int k = 0; k < BK; k++) {
            float ar[4], br[3];
#pragma unroll
            for (int i = 0; i < 4; i++) ar[i] = As[k][ty * 4 + i];
#pragma unroll
            for (int j = 0; j < 3; j++) br[j] = Bs[k][tx * 3 + j];
#pragma unroll
            for (int i = 0; i < 4; i++)
#pragma unroll
                for (int j = 0; j < 3; j++) acc[i][j] = fmaf(ar[i], br[j], acc[i][j]);
        }
        __syncthreads();
    }
    float* outp = g_xp + (size_t)kz * (BL_ * 96);
#pragma unroll
    for (int i = 0; i < 4; i++)
#pragma unroll
        for (int j = 0; j < 3; j++)
            outp[(size_t)(bm + ty * 4 + i) * 96 + tx * 3 + j] = acc[i][j];
}

__global__ void xproj_reduce_kernel() {
    int i = blockIdx.x * 256 + threadIdx.x;
    const size_t S = (size_t)BL_ * 96;
    g_xdbl[i] = g_xp[i] + g_xp[i + S] + g_xp[i + 2 * S] + g_xp[i + 3 * S];
}

// ---------------- selective scan v2: precompute + FMA chain -----------------
// Block: 128 threads = 8 channels x 16 states. Per 32-step chunk:
//  A) parallel: dA = exp(dt*a), xin = dt*u*B  -> smem
//  B) sequential per thread: h = fma(h, dA, xin); h -> smem (overwrites dA)
//  C) parallel: y[tt][c] = sum_n h*C, fuse D-skip + silu(z) gate -> staged write
__global__ __launch_bounds__(128) void scan_kernel(const float* __restrict__ A_log,
                                                   const float* __restrict__ Dp) {
    const int CH = 8;
    int b  = blockIdx.x / (E_ / CH);
    int e0 = (blockIdx.x % (E_ / CH)) * CH;
    int tid = threadIdx.x;
    int n = tid & 15, c = tid >> 4;
    int e = e0 + c;
    float a = -__expf(A_log[e * N_ + n]);
    float h = 0.f;
    __shared__ float s_dt[32][CH], s_u[32][CH], s_z[32][CH];
    __shared__ float s_bc[32][33];
    __shared__ float s_dA[32][129];   // reused as s_h in phase B/C
    __shared__ float s_x [32][129];
    __shared__ float s_y [32][9];
    __shared__ float s_d [CH];
    if (tid < CH) s_d[tid] = Dp[e0 + tid];

    for (int t0 = 0; t0 < L_; t0 += 32) {
#pragma unroll
        for (int r = 0; r < 2; r++) {
            int idx = tid + r * 128;
            int tt = idx >> 3, cc = idx & 7;
            int m = b * L_ + t0 + tt;
            size_t g = (size_t)m * E_ + e0 + cc;
            s_dt[tt][cc] = g_dt[g];
            s_u[tt][cc]  = g_u[g];
            s_z[tt][cc]  = g_xz[(size_t)m * E2_ + E_ + e0 + cc];
        }
#pragma unroll
        for (int r = 0; r < 8; r++) {
            int idx = tid + r * 128;
            int tt = idx >> 5, cc = idx & 31;
            s_bc[tt][cc] = g_xdbl[(size_t)(b * L_ + t0 + tt) * 96 + 64 + cc];
        }
        __syncthreads();
        // phase A: off-critical-path exp / products
#pragma unroll 8
        for (int tt = 0; tt < 32; tt++) {
            float dtv = s_dt[tt][c];
            s_dA[tt][tid] = __expf(dtv * a);
            s_x[tt][tid]  = dtv * s_u[tt][c] * s_bc[tt][n];
        }
        __syncthreads();
        // phase B: pure FMA recurrence (critical path)
#pragma unroll
        for (int tt = 0; tt < 32; tt++) {
            h = fmaf(h, s_dA[tt][tid], s_x[tt][tid]);
            s_dA[tt][tid] = h;     // becomes s_h
        }
        __syncthreads();
        // phase C: parallel reduction over n + gate
#pragma unroll
        for (int r = 0; r < 2; r++) {
            int idx = tid + r * 128;
            int tt = idx & 31, cc = idx >> 5;
            float y = 0.f;
#pragma unroll
            for (int q = 0; q < 16; q++)
                y = fmaf(s_dA[tt][cc * 16 + q], s_bc[tt][16 + q], y);
            float uv = s_u[tt][cc];
            float zv = s_z[tt][cc];
            float yv = fmaf(uv, s_d[cc], y);
            yv = yv * (zv / (1.f + __expf(-zv)));
            s_y[tt][cc] = yv;
        }
        __syncthreads();
        // coalesced tf32-rounded store
#pragma unroll
        for (int r = 0; r < 2; r++) {
            int idx = tid + r * 128;
            int tt = idx >> 3, cc = idx & 7;
            g_y[(size_t)(b * L_ + t0 + tt) * E_ + e0 + cc] = tf32_round(s_y[tt][cc]);
        }
        __syncthreads();
    }
}

// ---------------- launch ----------------------------------------------------
extern "C" void kernel_launch(void* const* d_in, const int* in_sizes, int n_in,
                              void* d_out, int out_size) {
    const float* x         = (const float*)d_in[0];
    const float* norm_w    = (const float*)d_in[1];
    const float* in_proj_w = (const float*)d_in[2];
    const float* conv_w    = (const float*)d_in[3];
    const float* conv_b    = (const float*)d_in[4];
    const float* x_proj_w  = (const float*)d_in[5];
    const float* dt_proj_w = (const float*)d_in[6];
    const float* dt_proj_b = (const float*)d_in[7];
    const float* A_log     = (const float*)d_in[8];
    const float* Dp        = (const float*)d_in[9];
    const float* out_proj_w= (const float*)d_in[10];
    float* out = (float*)d_out;

    float *p_xz, *p_dt, *p_xdbl, *p_xn, *p_wi, *p_wo, *p_y;
    cudaGetSymbolAddress((void**)&p_xz,   g_xz);
    cudaGetSymbolAddress((void**)&p_dt,   g_dt);
    cudaGetSymbolAddress((void**)&p_xdbl, g_xdbl);
    cudaGetSymbolAddress((void**)&p_xn,   g_xn);
    cudaGetSymbolAddress((void**)&p_wi,   g_wi);
    cudaGetSymbolAddress((void**)&p_wo,   g_wo);
    cudaGetSymbolAddress((void**)&p_y,    g_y);

    cudaFuncSetAttribute(gemm_tf32<0>, cudaFuncAttributeMaxDynamicSharedMemorySize, GEMM_SMEM);
    cudaFuncSetAttribute(gemm_tf32<2>, cudaFuncAttributeMaxDynamicSharedMemorySize, GEMM_SMEM);

    // 0) tf32-round weights
    cvt_tf32_kernel<<<(E2_ * DM_ / 4 + 255) / 256, 256>>>(in_proj_w, p_wi, E2_ * DM_ / 4);
    cvt_tf32_kernel<<<(DM_ * E_ / 4 + 255) / 256, 256>>>(out_proj_w, p_wo, DM_ * E_ / 4);
    // 1) RMSNorm (tf32-rounded)
    rmsnorm_kernel<<<BL_, 256>>>(x, norm_w);
    // 2) in_proj (tf32 HMMA): xz[4096,4096]
    gemm_tf32<0><<<dim3(E2_ / 128, BL_ / 128), 256, GEMM_SMEM>>>(
        p_xn, DM_, p_wi, DM_, nullptr, p_xz, E2_, DM_);
    // 3) depthwise causal conv + SiLU -> u
    conv_silu_kernel<<<(BL_ * E_) / 256, 256>>>(conv_w, conv_b);
    // 4) x_proj split-K x4 + reduce -> x_dbl [4096,96]
    xproj_part_kernel<<<dim3(BL_ / 32, 4), 256>>>(x_proj_w);
    xproj_reduce_kernel<<<(BL_ * 96) / 256, 256>>>();
    // 5) dt = softplus(dt_low @ dt_proj_w^T + b)
    gemm_tn<1><<<dim3(E_ / 128, BL_ / 128), 256>>>(
        p_xdbl, 96, dt_proj_w, R_, dt_proj_b, nullptr, p_dt, E_, R_);
    // 6) selective scan v2 -> y (tf32-rounded)
    scan_kernel<<<B_ * (E_ / 8), 128>>>(A_log, Dp);
    // 7) out_proj (tf32 HMMA) + residual
    gemm_tf32<2><<<dim3(DM_ / 128, BL_ / 128), 256, GEMM_SMEM>>>(
        p_y, E_, p_wo, E_, x, out, DM_, E_);
}

// round 6
// speedup vs baseline: 2.9608x; 1.7011x over previous
#include <cuda_runtime.h>
#include <cuda_bf16.h>
#include <cstdint>

// Problem constants
#define B_  2
#define L_  2048
#define DM_ 1024
#define E_  2048
#define N_  16
#define KC_ 4
#define R_  64
#define BL_ (B_ * L_)   // 4096
#define E2_ (2 * E_)    // 4096

// ---------------- scratch (static device memory) ----------------------------
__device__ float g_xz  [BL_ * E2_];          // in_proj output (u_pre | z)
__device__ float g_u   [BL_ * E_];           // post conv+silu
__device__ float g_xdbl[BL_ * 96];           // x_proj output (dt_low|B|C)
__device__ float g_xp  [4 * BL_ * 96];       // x_proj split-K partials
__device__ float g_xn  [BL_ * DM_];          // rmsnorm out (tf32-rounded fp32)
__device__ float g_wi  [E2_ * DM_];          // in_proj_w  (tf32-rounded)
__device__ float g_wo  [DM_ * E_];           // out_proj_w (tf32-rounded)
__device__ float g_y   [BL_ * E_];           // scan out (tf32-rounded)

// ---------------- PTX helpers -----------------------------------------------
__device__ __forceinline__ uint32_t smem_u32(const void* p) {
    return (uint32_t)__cvta_generic_to_shared(p);
}
__device__ __forceinline__ void cp_async16(uint32_t dst, const void* src) {
    asm volatile("cp.async.cg.shared.global [%0], [%1], 16;\n" :: "r"(dst), "l"(src));
}
#define CP_COMMIT() asm volatile("cp.async.commit_group;\n" ::: "memory")
#define CP_WAIT(n)  asm volatile("cp.async.wait_group %0;\n" :: "n"(n) : "memory")

#define LDSM4(r0, r1, r2, r3, addr) \
    asm volatile("ldmatrix.sync.aligned.m8n8.x4.shared.b16 {%0,%1,%2,%3}, [%4];" \
        : "=r"(r0), "=r"(r1), "=r"(r2), "=r"(r3) : "r"(addr))
#define LDSM2(r0, r1, addr) \
    asm volatile("ldmatrix.sync.aligned.m8n8.x2.shared.b16 {%0,%1}, [%2];" \
        : "=r"(r0), "=r"(r1) : "r"(addr))

#define MMATF32(c, a, b) \
    asm volatile("mma.sync.aligned.m16n8k8.row.col.f32.tf32.tf32.f32 " \
        "{%0,%1,%2,%3}, {%4,%5,%6,%7}, {%8,%9}, {%0,%1,%2,%3};" \
        : "+f"((c)[0]), "+f"((c)[1]), "+f"((c)[2]), "+f"((c)[3]) \
        : "r"((a)[0]), "r"((a)[1]), "r"((a)[2]), "r"((a)[3]), "r"((b)[0]), "r"((b)[1]))

__device__ __forceinline__ float tf32_round(float v) {
    float o;
    asm("cvt.rna.tf32.f32 %0, %1;" : "=f"(o) : "f"(v));
    return o;
}

// ---------------- fp32 -> tf32-rounded fp32 copy ----------------------------
__global__ void cvt_tf32_kernel(const float* __restrict__ src,
                                float* __restrict__ dst, int n4) {
    int i = blockIdx.x * 256 + threadIdx.x;
    if (i >= n4) return;
    float4 v = ((const float4*)src)[i];
    v.x = tf32_round(v.x); v.y = tf32_round(v.y);
    v.z = tf32_round(v.z); v.w = tf32_round(v.w);
    ((float4*)dst)[i] = v;
}

// ---------------- RMSNorm -> tf32-rounded fp32 -------------------------------
__global__ void rmsnorm_kernel(const float* __restrict__ x,
                               const float* __restrict__ w) {
    int row = blockIdx.x;
    const float* xr = x + (size_t)row * DM_;
    float s = 0.f;
    for (int i = threadIdx.x; i < DM_; i += 256) { float v = xr[i]; s += v * v; }
    __shared__ float red[8];
    for (int o = 16; o; o >>= 1) s += __shfl_xor_sync(0xffffffffu, s, o);
    if ((threadIdx.x & 31) == 0) red[threadIdx.x >> 5] = s;
    __syncthreads();
    if (threadIdx.x < 8) {
        float v = red[threadIdx.x];
        for (int o = 4; o; o >>= 1) v += __shfl_xor_sync(0xffu, v, o);
        if (threadIdx.x == 0) red[0] = v;
    }
    __syncthreads();
    float inv = rsqrtf(red[0] * (1.f / DM_) + 1e-5f);
    size_t base = (size_t)row * DM_;
    for (int i = threadIdx.x; i < DM_; i += 256)
        g_xn[base + i] = tf32_round(xr[i] * inv * w[i]);
}

// ---------------- tf32 HMMA GEMM (unchanged from R4) ------------------------
#define TTILE 16384
#define GEMM_SMEM (1024 + 4 * TTILE)

template <int MODE>
__global__ __launch_bounds__(256, 2) void gemm_tf32(
    const float* __restrict__ A, int lda,
    const float* __restrict__ B, int ldb,
    const float* __restrict__ resid, float* __restrict__ C, int ldc, int Kd) {
    extern __shared__ char smem[];
    uint32_t sb = smem_u32(smem);
    uint32_t tb0 = (sb + 1023u) & ~1023u;
    int tid = threadIdx.x, wid = tid >> 5, lid = tid & 31;
    int wm = wid >> 2, wn = wid & 3;

    int bm = blockIdx.y * 128, bn = blockIdx.x * 128;
    const int NC = Kd >> 5;

    auto load_tile = [&](uint32_t dst, const float* g, int row0, int ld, int k0) {
#pragma unroll
        for (int it = 0; it < 4; it++) {
            int idx = tid + it * 256;
            int r = idx >> 3, c16 = idx & 7;
            uint32_t off = (uint32_t)(r * 128 + ((c16 ^ (r & 7)) << 4));
            cp_async16(dst + off, g + (size_t)(row0 + r) * ld + k0 + c16 * 4);
        }
    };
    auto load_chunk = [&](int stage, int k0) {
        uint32_t tb = tb0 + stage * 2 * TTILE;
        load_tile(tb,         A, bm, lda, k0);
        load_tile(tb + TTILE, B, bn, ldb, k0);
        CP_COMMIT();
    };

    float acc[4][4][4];
#pragma unroll
    for (int i = 0; i < 4; i++)
#pragma unroll
        for (int j = 0; j < 4; j++)
#pragma unroll
            for (int q = 0; q < 4; q++) acc[i][j][q] = 0.f;

    load_chunk(0, 0);
    for (int ci = 0; ci < NC; ci++) {
        int s = ci & 1;
        if (ci + 1 < NC) { load_chunk((ci + 1) & 1, (ci + 1) * 32); CP_WAIT(1); }
        else             { CP_WAIT(0); }
        __syncthreads();
        uint32_t tA = tb0 + s * 2 * TTILE;
        uint32_t tB = tA + TTILE;
#pragma unroll
        for (int kk = 0; kk < 4; kk++) {
            uint32_t a[4][4];
#pragma unroll
            for (int i = 0; i < 4; i++) {
                int row = wm * 64 + i * 16 + (lid & 15);
                uint32_t chunk = (uint32_t)((kk * 2 + (lid >> 4)) ^ (row & 7));
                LDSM4(a[i][0], a[i][1], a[i][2], a[i][3],
                      tA + (uint32_t)(row * 128) + (chunk << 4));
            }
#pragma unroll
            for (int j = 0; j < 4; j++) {
                int row = wn * 32 + j * 8 + (lid & 7);
                uint32_t chunk = (uint32_t)((kk * 2 + ((lid >> 3) & 1)) ^ (row & 7));
                uint32_t b[2];
                LDSM2(b[0], b[1], tB + (uint32_t)(row * 128) + (chunk << 4));
#pragma unroll
                for (int i = 0; i < 4; i++) MMATF32(acc[i][j], a[i], b);
            }
        }
        __syncthreads();
    }

    int r0 = bm + wm * 64 + (lid >> 2);
    int c0 = bn + wn * 32 + (lid & 3) * 2;
#pragma unroll
    for (int i = 0; i < 4; i++) {
#pragma unroll
        for (int j = 0; j < 4; j++) {
            int r = r0 + i * 16, c = c0 + j * 8;
            float2 v0 = {acc[i][j][0], acc[i][j][1]};
            float2 v1 = {acc[i][j][2], acc[i][j][3]};
            if (MODE == 2) {
                const float2 q0 = *(const float2*)(resid + (size_t)r * ldc + c);
                const float2 q1 = *(const float2*)(resid + (size_t)(r + 8) * ldc + c);
                v0.x += q0.x; v0.y += q0.y; v1.x += q1.x; v1.y += q1.y;
            }
            *(float2*)(C + (size_t)r * ldc + c) = v0;
            *(float2*)(C + (size_t)(r + 8) * ldc + c) = v1;
        }
    }
}

// ---------------- causal depthwise conv (K=4) + SiLU, float4 ----------------
__global__ void conv_silu_kernel(const float* __restrict__ cw,
                                 const float* __restrict__ cb) {
    int idx = blockIdx.x * 256 + threadIdx.x;    // over BL*E/4
    int e4 = (idx & 511) * 4;
    int m = idx >> 9;
    int t = m & (L_ - 1);
    float4 acc = *(const float4*)(cb + e4);
    float4 w0 = *(const float4*)(cw + (size_t)(e4 + 0) * 4);
    float4 w1 = *(const float4*)(cw + (size_t)(e4 + 1) * 4);
    float4 w2 = *(const float4*)(cw + (size_t)(e4 + 2) * 4);
    float4 w3 = *(const float4*)(cw + (size_t)(e4 + 3) * 4);
    const float* base = g_xz + (size_t)m * E2_ + e4;
    const float* wp0 = (const float*)&w0;
    const float* wp1 = (const float*)&w1;
    const float* wp2 = (const float*)&w2;
    const float* wp3 = (const float*)&w3;
#pragma unroll
    for (int j = 0; j < KC_; j++) {
        int ts = t - (KC_ - 1) + j;
        if (ts >= 0) {
            float4 v = *(const float4*)(base + (ptrdiff_t)(j - (KC_ - 1)) * E2_);
            acc.x = fmaf(wp0[j], v.x, acc.x);
            acc.y = fmaf(wp1[j], v.y, acc.y);
            acc.z = fmaf(wp2[j], v.z, acc.z);
            acc.w = fmaf(wp3[j], v.w, acc.w);
        }
    }
    acc.x = acc.x / (1.f + __expf(-acc.x));
    acc.y = acc.y / (1.f + __expf(-acc.y));
    acc.z = acc.z / (1.f + __expf(-acc.z));
    acc.w = acc.w / (1.f + __expf(-acc.w));
    *(float4*)(g_u + (size_t)m * E_ + e4) = acc;
}

// ---------------- x_proj split-K partials: 4 x [BL, 96] ---------------------
__global__ __launch_bounds__(256) void xproj_part_kernel(const float* __restrict__ W) {
    const int BK = 32;
    __shared__ float As[BK][32];
    __shared__ float Bs[BK][96];
    int bm = blockIdx.x * 32;
    int kz = blockIdx.y;
    int tid = threadIdx.x;
    int tx = tid & 31;
    int ty = tid >> 5;
    float acc[4][3];
#pragma unroll
    for (int i = 0; i < 4; i++)
#pragma unroll
        for (int j = 0; j < 3; j++) acc[i][j] = 0.f;

    int alr = tid >> 3, alc = (tid & 7) * 4;
    int kbeg = kz * (E_ / 4), kend = kbeg + (E_ / 4);
    for (int k0 = kbeg; k0 < kend; k0 += BK) {
        float4 a = *(const float4*)(g_u + (size_t)(bm + alr) * E_ + k0 + alc);
        As[alc + 0][alr] = a.x; As[alc + 1][alr] = a.y;
        As[alc + 2][alr] = a.z; As[alc + 3][alr] = a.w;
#pragma unroll
        for (int r = 0; r < 3; r++) {
            int s = tid + r * 256;
            int fr = s >> 3, fc = (s & 7) * 4;
            float4 b = *(const float4*)(W + (size_t)fr * E_ + k0 + fc);
            Bs[fc + 0][fr] = b.x; Bs[fc + 1][fr] = b.y;
            Bs[fc + 2][fr] = b.z; Bs[fc + 3][fr] = b.w;
        }
        __syncthreads();
#pragma unroll
        for (int k = 0; k < BK; k++) {
            float ar[4], br[3];
#pragma unroll
            for (int i = 0; i < 4; i++) ar[i] = As[k][ty * 4 + i];
#pragma unroll
            for (int j = 0; j < 3; j++) br[j] = Bs[k][tx * 3 + j];
#pragma unroll
            for (int i = 0; i < 4; i++)
#pragma unroll
                for (int j = 0; j < 3; j++) acc[i][j] = fmaf(ar[i], br[j], acc[i][j]);
        }
        __syncthreads();
    }
    float* outp = g_xp + (size_t)kz * (BL_ * 96);
#pragma unroll
    for (int i = 0; i < 4; i++)
#pragma unroll
        for (int j = 0; j < 3; j++)
            outp[(size_t)(bm + ty * 4 + i) * 96 + tx * 3 + j] = acc[i][j];
}

__global__ void xproj_reduce_kernel() {
    int i = blockIdx.x * 256 + threadIdx.x;
    const size_t S = (size_t)BL_ * 96;
    g_xdbl[i] = g_xp[i] + g_xp[i + S] + g_xp[i + 2 * S] + g_xp[i + 3 * S];
}

// ---------------- selective scan v3 + fused dt projection -------------------
// Block: 128 thr = 8 channels x 16 states. Per 32-step chunk (double-buffered
// cp.async): fused softplus(dtlow@Wdt+b), register dA/x, serial FMA chain,
// parallel C-reduction + D-skip + silu(z) gate.
struct ScanSmem {
    float w[8][64];           // dt_proj_w rows for this block's 8 channels
    float db[8], d[8];
    float xd[2][32][100];     // g_xdbl rows (96 cols, pad 100)
    float u[2][32][12];       // g_u slice   (8 cols, pad 12 for 16B rows)
    float z[2][32][12];       // z slice
    float dt[32][9];
    float h[32][129];
};
#define SCAN_SMEM ((int)sizeof(ScanSmem))

__global__ __launch_bounds__(128) void scan_kernel(const float* __restrict__ A_log,
                                                   const float* __restrict__ Dp,
                                                   const float* __restrict__ Wdt,
                                                   const float* __restrict__ bdt) {
    extern __shared__ char sraw[];
    ScanSmem* ss = (ScanSmem*)sraw;
    const int CH = 8;
    int b  = blockIdx.x / (E_ / CH);
    int e0 = (blockIdx.x % (E_ / CH)) * CH;
    int tid = threadIdx.x;
    int n = tid & 15, c = tid >> 4;
    int e = e0 + c;

    for (int i = tid; i < CH * 64; i += 128)
        ss->w[i >> 6][i & 63] = Wdt[(size_t)(e0 + (i >> 6)) * R_ + (i & 63)];
    if (tid < CH) { ss->db[tid] = bdt[e0 + tid]; ss->d[tid] = Dp[e0 + tid]; }

    float a = -__expf(A_log[e * N_ + n]);
    float h = 0.f;

    auto prefetch = [&](int st, int t0) {
        int m0 = b * L_ + t0;
#pragma unroll
        for (int it = 0; it < 6; it++) {      // 768 16B-chunks of xd
            int idx = tid + it * 128;
            int r = idx / 24, c4 = (idx % 24) * 4;
            cp_async16(smem_u32(&ss->xd[st][r][c4]),
                       g_xdbl + (size_t)(m0 + r) * 96 + c4);
        }
        if (tid < 64) {
            int r = tid >> 1, hf = (tid & 1) * 4;
            cp_async16(smem_u32(&ss->u[st][r][hf]),
                       g_u + (size_t)(m0 + r) * E_ + e0 + hf);
        } else {
            int q = tid - 64;
            int r = q >> 1, hf = (q & 1) * 4;
            cp_async16(smem_u32(&ss->z[st][r][hf]),
                       g_xz + (size_t)(m0 + r) * E2_ + E_ + e0 + hf);
        }
        CP_COMMIT();
    };

    prefetch(0, 0);
    for (int t0 = 0; t0 < L_; t0 += 32) {
        int st = (t0 >> 5) & 1;
        if (t0 + 32 < L_) { prefetch(st ^ 1, t0 + 32); CP_WAIT(1); }
        else              { CP_WAIT(0); }
        __syncthreads();

        // fused dt: outputs (tt, c2), (tt, c2+4)
        {
            int tt = tid & 31, c2 = tid >> 5;
            float a0 = ss->db[c2], a1 = ss->db[c2 + 4];
#pragma unroll
            for (int k = 0; k < 64; k++) {
                float xv = ss->xd[st][tt][k];
                a0 = fmaf(xv, ss->w[c2][k], a0);
                a1 = fmaf(xv, ss->w[c2 + 4][k], a1);
            }
            ss->dt[tt][c2]     = (a0 > 20.f) ? a0 : log1pf(__expf(a0));
            ss->dt[tt][c2 + 4] = (a1 > 20.f) ? a1 : log1pf(__expf(a1));
        }
        __syncthreads();

        // recurrence in registers
        float hh = h;
#pragma unroll
        for (int tt = 0; tt < 32; tt++) {
            float dtv = ss->dt[tt][c];
            float dA = __expf(dtv * a);
            float xv = dtv * ss->u[st][tt][c] * ss->xd[st][tt][64 + n];
            hh = fmaf(hh, dA, xv);
            ss->h[tt][tid] = hh;
        }
        h = hh;
        __syncthreads();

        // C-reduction + gate, coalesced-ish 32B stores
#pragma unroll
        for (int r = 0; r < 2; r++) {
            int idx = tid + r * 128;
            int tt = idx >> 3, cc = idx & 7;
            float y = 0.f;
#pragma unroll
            for (int q = 0; q < 16; q++)
                y = fmaf(ss->h[tt][cc * 16 + q], ss->xd[st][tt][80 + q], y);
            float uv = ss->u[st][tt][cc];
            float zv = ss->z[st][tt][cc];
            float yv = fmaf(uv, ss->d[cc], y);
            yv = yv * (zv / (1.f + __expf(-zv)));
            g_y[(size_t)(b * L_ + t0 + tt) * E_ + e0 + cc] = tf32_round(yv);
        }
        __syncthreads();
    }
}

// ---------------- launch ----------------------------------------------------
extern "C" void kernel_launch(void* const* d_in, const int* in_sizes, int n_in,
                              void* d_out, int out_size) {
    const float* x         = (const float*)d_in[0];
    const float* norm_w    = (const float*)d_in[1];
    const float* in_proj_w = (const float*)d_in[2];
    const float* conv_w    = (const float*)d_in[3];
    const float* conv_b    = (const float*)d_in[4];
    const float* x_proj_w  = (const float*)d_in[5];
    const float* dt_proj_w = (const float*)d_in[6];
    const float* dt_proj_b = (const float*)d_in[7];
    const float* A_log     = (const float*)d_in[8];
    const float* Dp        = (const float*)d_in[9];
    const float* out_proj_w= (const float*)d_in[10];
    float* out = (float*)d_out;

    float *p_xz, *p_xn, *p_wi, *p_wo, *p_y;
    cudaGetSymbolAddress((void**)&p_xz, g_xz);
    cudaGetSymbolAddress((void**)&p_xn, g_xn);
    cudaGetSymbolAddress((void**)&p_wi, g_wi);
    cudaGetSymbolAddress((void**)&p_wo, g_wo);
    cudaGetSymbolAddress((void**)&p_y,  g_y);

    cudaFuncSetAttribute(gemm_tf32<0>, cudaFuncAttributeMaxDynamicSharedMemorySize, GEMM_SMEM);
    cudaFuncSetAttribute(gemm_tf32<2>, cudaFuncAttributeMaxDynamicSharedMemorySize, GEMM_SMEM);
    cudaFuncSetAttribute(scan_kernel,  cudaFuncAttributeMaxDynamicSharedMemorySize, SCAN_SMEM);

    // 0) tf32-round weights
    cvt_tf32_kernel<<<(E2_ * DM_ / 4 + 255) / 256, 256>>>(in_proj_w, p_wi, E2_ * DM_ / 4);
    cvt_tf32_kernel<<<(DM_ * E_ / 4 + 255) / 256, 256>>>(out_proj_w, p_wo, DM_ * E_ / 4);
    // 1) RMSNorm (tf32-rounded)
    rmsnorm_kernel<<<BL_, 256>>>(x, norm_w);
    // 2) in_proj (tf32 HMMA): xz[4096,4096]
    gemm_tf32<0><<<dim3(E2_ / 128, BL_ / 128), 256, GEMM_SMEM>>>(
        p_xn, DM_, p_wi, DM_, nullptr, p_xz, E2_, DM_);
    // 3) depthwise causal conv + SiLU -> u (float4)
    conv_silu_kernel<<<(BL_ * E_ / 4) / 256, 256>>>(conv_w, conv_b);
    // 4) x_proj split-K x4 + reduce -> x_dbl [4096,96]
    xproj_part_kernel<<<dim3(BL_ / 32, 4), 256>>>(x_proj_w);
    xproj_reduce_kernel<<<(BL_ * 96) / 256, 256>>>();
    // 5+6) selective scan with fused dt projection -> y (tf32-rounded)
    scan_kernel<<<B_ * (E_ / 8), 128, SCAN_SMEM>>>(A_log, Dp, dt_proj_w, dt_proj_b);
    // 7) out_proj (tf32 HMMA) + residual
    gemm_tf32<2><<<dim3(DM_ / 128, BL_ / 128), 256, GEMM_SMEM>>>(
        p_y, E_, p_wo, E_, x, out, DM_, E_);
}

// round 8
// speedup vs baseline: 3.2966x; 1.1134x over previous
#include <cuda_runtime.h>
#include <cuda_bf16.h>
#include <cstdint>

// Problem constants
#define B_  2
#define L_  2048
#define DM_ 1024
#define E_  2048
#define N_  16
#define KC_ 4
#define R_  64
#define BL_ (B_ * L_)   // 4096
#define E2_ (2 * E_)    // 4096

// ---------------- scratch (static device memory) ----------------------------
__device__ float g_xz  [BL_ * E2_];          // in_proj output (u_pre | z)
__device__ float g_u   [BL_ * E_];           // post conv+silu (tf32-rounded)
__device__ float g_xdbl[BL_ * 96];           // x_proj output (dt_low|B|C)
__device__ float g_xp  [4 * BL_ * 128];      // x_proj split-K partials (padded N=128)
__device__ float g_xpw [128 * E_];           // x_proj_w padded to 128 rows (tf32)
__device__ float g_xn  [BL_ * DM_];          // rmsnorm out (tf32-rounded fp32)
__device__ float g_wi  [E2_ * DM_];          // in_proj_w  (tf32-rounded)
__device__ float g_wo  [DM_ * E_];           // out_proj_w (tf32-rounded)
__device__ float g_y   [BL_ * E_];           // scan out (tf32-rounded)

// ---------------- PTX helpers -----------------------------------------------
__device__ __forceinline__ uint32_t smem_u32(const void* p) {
    return (uint32_t)__cvta_generic_to_shared(p);
}
__device__ __forceinline__ void cp_async16(uint32_t dst, const void* src) {
    asm volatile("cp.async.cg.shared.global [%0], [%1], 16;\n" :: "r"(dst), "l"(src));
}
#define CP_COMMIT() asm volatile("cp.async.commit_group;\n" ::: "memory")
#define CP_WAIT(n)  asm volatile("cp.async.wait_group %0;\n" :: "n"(n) : "memory")

#define LDSM4(r0, r1, r2, r3, addr) \
    asm volatile("ldmatrix.sync.aligned.m8n8.x4.shared.b16 {%0,%1,%2,%3}, [%4];" \
        : "=r"(r0), "=r"(r1), "=r"(r2), "=r"(r3) : "r"(addr))
#define LDSM2(r0, r1, addr) \
    asm volatile("ldmatrix.sync.aligned.m8n8.x2.shared.b16 {%0,%1}, [%2];" \
        : "=r"(r0), "=r"(r1) : "r"(addr))

#define MMATF32(c, a, b) \
    asm volatile("mma.sync.aligned.m16n8k8.row.col.f32.tf32.tf32.f32 " \
        "{%0,%1,%2,%3}, {%4,%5,%6,%7}, {%8,%9}, {%0,%1,%2,%3};" \
        : "+f"((c)[0]), "+f"((c)[1]), "+f"((c)[2]), "+f"((c)[3]) \
        : "r"((a)[0]), "r"((a)[1]), "r"((a)[2]), "r"((a)[3]), "r"((b)[0]), "r"((b)[1]))

__device__ __forceinline__ float tf32_round(float v) {
    float o;
    asm("cvt.rna.tf32.f32 %0, %1;" : "=f"(o) : "f"(v));
    return o;
}

// ---------------- fp32 -> tf32-rounded fp32 copy ----------------------------
__global__ void cvt_tf32_kernel(const float* __restrict__ src,
                                float* __restrict__ dst, int n4) {
    int i = blockIdx.x * 256 + threadIdx.x;
    if (i >= n4) return;
    float4 v = ((const float4*)src)[i];
    v.x = tf32_round(v.x); v.y = tf32_round(v.y);
    v.z = tf32_round(v.z); v.w = tf32_round(v.w);
    ((float4*)dst)[i] = v;
}

// ---------------- x_proj_w -> padded [128][E], tf32-rounded, rows 96+ zero --
__global__ void xpad_kernel(const float* __restrict__ W) {
    int i = blockIdx.x * 256 + threadIdx.x;   // over 128*E/4
    int row = (i * 4) >> 11;                  // /E_
    float4 v = {0.f, 0.f, 0.f, 0.f};
    if (row < 96) {
        v = ((const float4*)W)[i];
        v.x = tf32_round(v.x); v.y = tf32_round(v.y);
        v.z = tf32_round(v.z); v.w = tf32_round(v.w);
    }
    ((float4*)g_xpw)[i] = v;
}

// ---------------- RMSNorm -> tf32-rounded fp32 -------------------------------
__global__ void rmsnorm_kernel(const float* __restrict__ x,
                               const float* __restrict__ w) {
    int row = blockIdx.x;
    const float* xr = x + (size_t)row * DM_;
    float s = 0.f;
    for (int i = threadIdx.x; i < DM_; i += 256) { float v = xr[i]; s += v * v; }
    __shared__ float red[8];
    for (int o = 16; o; o >>= 1) s += __shfl_xor_sync(0xffffffffu, s, o);
    if ((threadIdx.x & 31) == 0) red[threadIdx.x >> 5] = s;
    __syncthreads();
    if (threadIdx.x < 8) {
        float v = red[threadIdx.x];
        for (int o = 4; o; o >>= 1) v += __shfl_xor_sync(0xffu, v, o);
        if (threadIdx.x == 0) red[0] = v;
    }
    __syncthreads();
    float inv = rsqrtf(red[0] * (1.f / DM_) + 1e-5f);
    size_t base = (size_t)row * DM_;
    for (int i = threadIdx.x; i < DM_; i += 256)
        g_xn[base + i] = tf32_round(xr[i] * inv * w[i]);
}

// ---------------- tf32 HMMA GEMM, 3-stage cp.async pipeline -----------------
// C[m,n] = sum_k A[m,k]*B[n,k].  MODE 0: plain (z-split aware)  MODE 2: +resid
// CTA 128x128, 8 warps (2Mx4N), K-chunk 32 fp32 (128B SW128 rows).
// gridDim.z splits K; partial z writes to C + z*M*ldc.
#define TTILE 16384
#define GEMM_SMEM (1024 + 6 * TTILE)   // 3 stages x (A + B)

template <int MODE>
__global__ __launch_bounds__(256, 2) void gemm_tf32(
    const float* __restrict__ A, int lda,
    const float* __restrict__ B, int ldb,
    const float* __restrict__ resid, float* __restrict__ C, int ldc, int Ksplit) {
    extern __shared__ char smem[];
    uint32_t sb = smem_u32(smem);
    uint32_t tb0 = (sb + 1023u) & ~1023u;
    int tid = threadIdx.x, wid = tid >> 5, lid = tid & 31;
    int wm = wid >> 2, wn = wid & 3;

    int bm = blockIdx.y * 128, bn = blockIdx.x * 128;
    int kbeg = blockIdx.z * Ksplit;
    size_t coff = (size_t)blockIdx.z * gridDim.y * 128 * ldc;
    const int NC = Ksplit >> 5;

    auto load_tile = [&](uint32_t dst, const float* g, int row0, int ld, int k0) {
#pragma unroll
        for (int it = 0; it < 4; it++) {
            int idx = tid + it * 256;
            int r = idx >> 3, c16 = idx & 7;
            uint32_t off = (uint32_t)(r * 128 + ((c16 ^ (r & 7)) << 4));
            cp_async16(dst + off, g + (size_t)(row0 + r) * ld + k0 + c16 * 4);
        }
    };
    auto load_chunk = [&](int stage, int k0) {
        uint32_t tb = tb0 + stage * 2 * TTILE;
        load_tile(tb,         A, bm, lda, k0);
        load_tile(tb + TTILE, B, bn, ldb, k0);
        CP_COMMIT();
    };

    float acc[4][4][4];
#pragma unroll
    for (int i = 0; i < 4; i++)
#pragma unroll
        for (int j = 0; j < 4; j++)
#pragma unroll
            for (int q = 0; q < 4; q++) acc[i][j][q] = 0.f;

    load_chunk(0, kbeg);
    if (NC > 1) load_chunk(1, kbeg + 32);
    for (int ci = 0; ci < NC; ci++) {
        int s = ci % 3;
        if (ci + 2 < NC) {
            __syncthreads();                      // buf (ci+2)%3 free (read at ci-1)
            load_chunk((ci + 2) % 3, kbeg + (ci + 2) * 32);
            CP_WAIT(2);
        } else if (ci + 1 < NC) {
            __syncthreads();
            CP_WAIT(1);
        } else {
            __syncthreads();
            CP_WAIT(0);
        }
        __syncthreads();                          // visibility of chunk ci
        uint32_t tA = tb0 + s * 2 * TTILE;
        uint32_t tB = tA + TTILE;
#pragma unroll
        for (int kk = 0; kk < 4; kk++) {
            uint32_t a[4][4];
#pragma unroll
            for (int i = 0; i < 4; i++) {
                int row = wm * 64 + i * 16 + (lid & 15);
                uint32_t chunk = (uint32_t)((kk * 2 + (lid >> 4)) ^ (row & 7));
                LDSM4(a[i][0], a[i][1], a[i][2], a[i][3],
                      tA + (uint32_t)(row * 128) + (chunk << 4));
            }
#pragma unroll
            for (int j = 0; j < 4; j++) {
                int row = wn * 32 + j * 8 + (lid & 7);
                uint32_t chunk = (uint32_t)((kk * 2 + ((lid >> 3) & 1)) ^ (row & 7));
                uint32_t b[2];
                LDSM2(b[0], b[1], tB + (uint32_t)(row * 128) + (chunk << 4));
#pragma unroll
                for (int i = 0; i < 4; i++) MMATF32(acc[i][j], a[i], b);
            }
        }
    }

    int r0 = bm + wm * 64 + (lid >> 2);
    int c0 = bn + wn * 32 + (lid & 3) * 2;
#pragma unroll
    for (int i = 0; i < 4; i++) {
#pragma unroll
        for (int j = 0; j < 4; j++) {
            int r = r0 + i * 16, c = c0 + j * 8;
            float2 v0 = {acc[i][j][0], acc[i][j][1]};
            float2 v1 = {acc[i][j][2], acc[i][j][3]};
            if (MODE == 2) {
                const float2 q0 = *(const float2*)(resid + (size_t)r * ldc + c);
                const float2 q1 = *(const float2*)(resid + (size_t)(r + 8) * ldc + c);
                v0.x += q0.x; v0.y += q0.y; v1.x += q1.x; v1.y += q1.y;
            }
            *(float2*)(C + coff + (size_t)r * ldc + c) = v0;
            *(float2*)(C + coff + (size_t)(r + 8) * ldc + c) = v1;
        }
    }
}

// ---------------- causal depthwise conv (K=4) + SiLU, float4, tf32 out ------
__global__ void conv_silu_kernel(const float* __restrict__ cw,
                                 const float* __restrict__ cb) {
    int idx = blockIdx.x * 256 + threadIdx.x;    // over BL*E/4
    int e4 = (idx & 511) * 4;
    int m = idx >> 9;
    int t = m & (L_ - 1);
    float4 acc = *(const float4*)(cb + e4);
    float4 w0 = *(const float4*)(cw + (size_t)(e4 + 0) * 4);
    float4 w1 = *(const float4*)(cw + (size_t)(e4 + 1) * 4);
    float4 w2 = *(const float4*)(cw + (size_t)(e4 + 2) * 4);
    float4 w3 = *(const float4*)(cw + (size_t)(e4 + 3) * 4);
    const float* base = g_xz + (size_t)m * E2_ + e4;
    const float* wp0 = (const float*)&w0;
    const float* wp1 = (const float*)&w1;
    const float* wp2 = (const float*)&w2;
    const float* wp3 = (const float*)&w3;
#pragma unroll
    for (int j = 0; j < KC_; j++) {
        int ts = t - (KC_ - 1) + j;
        if (ts >= 0) {
            float4 v = *(const float4*)(base + (ptrdiff_t)(j - (KC_ - 1)) * E2_);
            acc.x = fmaf(wp0[j], v.x, acc.x);
            acc.y = fmaf(wp1[j], v.y, acc.y);
            acc.z = fmaf(wp2[j], v.z, acc.z);
            acc.w = fmaf(wp3[j], v.w, acc.w);
        }
    }
    acc.x = tf32_round(acc.x / (1.f + __expf(-acc.x)));
    acc.y = tf32_round(acc.y / (1.f + __expf(-acc.y)));
    acc.z = tf32_round(acc.z / (1.f + __expf(-acc.z)));
    acc.w = tf32_round(acc.w / (1.f + __expf(-acc.w)));
    *(float4*)(g_u + (size_t)m * E_ + e4) = acc;
}

// ---------------- xproj reduce: sum 4 padded partials -> [BL][96] -----------
__global__ void xproj_reduce_kernel() {
    int i = blockIdx.x * 256 + threadIdx.x;   // over BL*96
    int r = i / 96, c = i - r * 96;
    const size_t S = (size_t)BL_ * 128;
    size_t p = (size_t)r * 128 + c;
    g_xdbl[i] = g_xp[p] + g_xp[p + S] + g_xp[p + 2 * S] + g_xp[p + 3 * S];
}

// ---------------- selective scan + fused dt projection ----------------------
struct ScanSmem {
    float w[8][64];           // dt_proj_w rows for this block's 8 channels
    float db[8], d[8];
    float xd[2][32][100];     // g_xdbl rows (96 cols, pad 100)
    float u[2][32][12];       // g_u slice (8 cols, pad 12)
    float z[2][32][12];       // z slice
    float dt[32][9];
    float h[32][129];
};
#define SCAN_SMEM ((int)sizeof(ScanSmem))

__global__ __launch_bounds__(128) void scan_kernel(const float* __restrict__ A_log,
                                                   const float* __restrict__ Dp,
                                                   const float* __restrict__ Wdt,
                                                   const float* __restrict__ bdt) {
    extern __shared__ char sraw[];
    ScanSmem* ss = (ScanSmem*)sraw;
    const int CH = 8;
    int b  = blockIdx.x / (E_ / CH);
    int e0 = (blockIdx.x % (E_ / CH)) * CH;
    int tid = threadIdx.x;
    int n = tid & 15, c = tid >> 4;
    int e = e0 + c;

    for (int i = tid; i < CH * 64; i += 128)
        ss->w[i >> 6][i & 63] = Wdt[(size_t)(e0 + (i >> 6)) * R_ + (i & 63)];
    if (tid < CH) { ss->db[tid] = bdt[e0 + tid]; ss->d[tid] = Dp[e0 + tid]; }

    float a = -__expf(A_log[e * N_ + n]);
    float h = 0.f;

    auto prefetch = [&](int st, int t0) {
        int m0 = b * L_ + t0;
#pragma unroll
        for (int it = 0; it < 6; it++) {
            int idx = tid + it * 128;
            int r = idx / 24, c4 = (idx % 24) * 4;
            cp_async16(smem_u32(&ss->xd[st][r][c4]),
                       g_xdbl + (size_t)(m0 + r) * 96 + c4);
        }
        if (tid < 64) {
            int r = tid >> 1, hf = (tid & 1) * 4;
            cp_async16(smem_u32(&ss->u[st][r][hf]),
                       g_u + (size_t)(m0 + r) * E_ + e0 + hf);
        } else {
            int q = tid - 64;
            int r = q >> 1, hf = (q & 1) * 4;
            cp_async16(smem_u32(&ss->z[st][r][hf]),
                       g_xz + (size_t)(m0 + r) * E2_ + E_ + e0 + hf);
        }
        CP_COMMIT();
    };

    prefetch(0, 0);
    for (int t0 = 0; t0 < L_; t0 += 32) {
        int st = (t0 >> 5) & 1;
        if (t0 + 32 < L_) { prefetch(st ^ 1, t0 + 32); CP_WAIT(1); }
        else              { CP_WAIT(0); }
        __syncthreads();

        // fused dt projection + softplus
        {
            int tt = tid & 31, c2 = tid >> 5;
            float a0 = ss->db[c2], a1 = ss->db[c2 + 4];
#pragma unroll
            for (int k = 0; k < 64; k++) {
                float xv = ss->xd[st][tt][k];
                a0 = fmaf(xv, ss->w[c2][k], a0);
                a1 = fmaf(xv, ss->w[c2 + 4][k], a1);
            }
            ss->dt[tt][c2]     = (a0 > 20.f) ? a0 : log1pf(__expf(a0));
            ss->dt[tt][c2 + 4] = (a1 > 20.f) ? a1 : log1pf(__expf(a1));
        }
        __syncthreads();

        // recurrence
        float hh = h;
#pragma unroll
        for (int tt = 0; tt < 32; tt++) {
            float dtv = ss->dt[tt][c];
            float dA = __expf(dtv * a);
            float xv = dtv * ss->u[st][tt][c] * ss->xd[st][tt][64 + n];
            hh = fmaf(hh, dA, xv);
            ss->h[tt][tid] = hh;
        }
        h = hh;
        __syncthreads();

        // C-reduction + D-skip + silu(z) gate
#pragma unroll
        for (int r = 0; r < 2; r++) {
            int idx = tid + r * 128;
            int tt = idx >> 3, cc = idx & 7;
            float y = 0.f;
#pragma unroll
            for (int q = 0; q < 16; q++)
                y = fmaf(ss->h[tt][cc * 16 + q], ss->xd[st][tt][80 + q], y);
            float uv = ss->u[st][tt][cc];
            float zv = ss->z[st][tt][cc];
            float yv = fmaf(uv, ss->d[cc], y);
            yv = yv * (zv / (1.f + __expf(-zv)));
            g_y[(size_t)(b * L_ + t0 + tt) * E_ + e0 + cc] = tf32_round(yv);
        }
        __syncthreads();
    }
}

// ---------------- launch ----------------------------------------------------
extern "C" void kernel_launch(void* const* d_in, const int* in_sizes, int n_in,
                              void* d_out, int out_size) {
    const float* x         = (const float*)d_in[0];
    const float* norm_w    = (const float*)d_in[1];
    const float* in_proj_w = (const float*)d_in[2];
    const float* conv_w    = (const float*)d_in[3];
    const float* conv_b    = (const float*)d_in[4];
    const float* x_proj_w  = (const float*)d_in[5];
    const float* dt_proj_w = (const float*)d_in[6];
    const float* dt_proj_b = (const float*)d_in[7];
    const float* A_log     = (const float*)d_in[8];
    const float* Dp        = (const float*)d_in[9];
    const float* out_proj_w= (const float*)d_in[10];
    float* out = (float*)d_out;

    float *p_xz, *p_xn, *p_wi, *p_wo, *p_y, *p_u, *p_xpw, *p_xp;
    cudaGetSymbolAddress((void**)&p_xz,  g_xz);
    cudaGetSymbolAddress((void**)&p_xn,  g_xn);
    cudaGetSymbolAddress((void**)&p_wi,  g_wi);
    cudaGetSymbolAddress((void**)&p_wo,  g_wo);
    cudaGetSymbolAddress((void**)&p_y,   g_y);
    cudaGetSymbolAddress((void**)&p_u,   g_u);
    cudaGetSymbolAddress((void**)&p_xpw, g_xpw);
    cudaGetSymbolAddress((void**)&p_xp,  g_xp);

    cudaFuncSetAttribute(gemm_tf32<0>, cudaFuncAttributeMaxDynamicSharedMemorySize, GEMM_SMEM);
    cudaFuncSetAttribute(gemm_tf32<2>, cudaFuncAttributeMaxDynamicSharedMemorySize, GEMM_SMEM);
    cudaFuncSetAttribute(scan_kernel,  cudaFuncAttributeMaxDynamicSharedMemorySize, SCAN_SMEM);

    // 0) weight prep (tf32 rounding; xproj padded to 128 rows)
    cvt_tf32_kernel<<<(E2_ * DM_ / 4 + 255) / 256, 256>>>(in_proj_w, p_wi, E2_ * DM_ / 4);
    cvt_tf32_kernel<<<(DM_ * E_ / 4 + 255) / 256, 256>>>(out_proj_w, p_wo, DM_ * E_ / 4);
    xpad_kernel<<<(128 * E_ / 4) / 256, 256>>>(x_proj_w);
    // 1) RMSNorm
    rmsnorm_kernel<<<BL_, 256>>>(x, norm_w);
    // 2) in_proj: xz[4096,4096] = xn @ wi^T
    gemm_tf32<0><<<dim3(E2_ / 128, BL_ / 128, 1), 256, GEMM_SMEM>>>(
        p_xn, DM_, p_wi, DM_, nullptr, p_xz, E2_, DM_);
    // 3) conv + SiLU -> u (tf32-rounded)
    conv_silu_kernel<<<(BL_ * E_ / 4) / 256, 256>>>(conv_w, conv_b);
    // 4) x_proj (HMMA, split-K x4, padded N=128) + reduce -> x_dbl[4096,96]
    gemm_tf32<0><<<dim3(1, BL_ / 128, 4), 256, GEMM_SMEM>>>(
        p_u, E_, p_xpw, E_, nullptr, p_xp, 128, E_ / 4);
    xproj_reduce_kernel<<<(BL_ * 96) / 256, 256>>>();
    // 5+6) selective scan with fused dt projection -> y
    scan_kernel<<<B_ * (E_ / 8), 128, SCAN_SMEM>>>(A_log, Dp, dt_proj_w, dt_proj_b);
    // 7) out_proj + residual
    gemm_tf32<2><<<dim3(DM_ / 128, BL_ / 128, 1), 256, GEMM_SMEM>>>(
        p_y, E_, p_wo, E_, x, out, DM_, E_);
}